// round 13
// baseline (speedup 1.0000x reference)
#include <cuda_runtime.h>
#include <cuda_fp16.h>
#include <math.h>
#include <stdint.h>

// ---------------- Problem constants (fixed shapes) ----------------
#define BATCH 2
#define SEQ   2048
#define NTOK  (BATCH*SEQ)        // 4096
#define HID   2048
#define NH    16
#define DQ    192
#define DNOPE 128
#define DROPE 64
#define DV    128
#define KVR   512
#define INTER 10944

// ---------------- Scratch (device globals; allocation-free) ----------------
__device__ __half h_xln [NTOK*HID];
__device__ __half h_cln [NTOK*KVR];
__device__ __half h_attn[NTOK*HID];
__device__ __half h_y   [NTOK*HID];
__device__ __half h_gg  [NTOK*INTER];
__device__ __half h_gh  [NTOK*INTER];
__device__ __half h_q   [NTOK*NH*DQ];
__device__ __half h_kv  [NTOK*NH*(DNOPE+DV)];
__device__ __half h_qf  [BATCH*NH*SEQ*DQ];
__device__ __half h_kf  [BATCH*NH*SEQ*DQ];
__device__ __half h_v   [BATCH*NH*SEQ*DV];
__device__ float g_ckv [NTOK*(KVR+DROPE)];
__device__ float g_x1  [NTOK*HID];
// fp16 weight copies
__device__ __half hw_q  [NH*DQ*HID];
__device__ __half hw_kva[(KVR+DROPE)*HID];
__device__ __half hw_kvb[NH*(DNOPE+DV)*KVR];
__device__ __half hw_o  [HID*NH*DV];
__device__ __half hw_g  [INTER*HID];
__device__ __half hw_u  [INTER*HID];
__device__ __half hw_d  [HID*INTER];

// ---------------- weight fp32 -> fp16 ----------------
__global__ void w2h_kernel(const float* __restrict__ in, __half* __restrict__ out, int n4) {
    int i = blockIdx.x * blockDim.x + threadIdx.x;
    if (i < n4) {
        float4 v = ((const float4*)in)[i];
        __half2 h0 = __floats2half2_rn(v.x, v.y);
        __half2 h1 = __floats2half2_rn(v.z, v.w);
        ((uint2*)out)[i] = make_uint2(*(uint32_t*)&h0, *(uint32_t*)&h1);
    }
}

// ---------------- RMSNorm (fp32 in, fp16 out) ----------------
__global__ void rmsnorm_kernel(const float* __restrict__ in, const float* __restrict__ w,
                               __half* __restrict__ out, int cols, int instride) {
    int row = blockIdx.x;
    int tid = threadIdx.x;
    const float* xr = in + (size_t)row * instride;
    float s = 0.f;
    for (int c = tid; c < cols; c += 256) { float v = xr[c]; s += v * v; }
    __shared__ float red[8];
    for (int o = 16; o; o >>= 1) s += __shfl_xor_sync(0xffffffffu, s, o);
    if ((tid & 31) == 0) red[tid >> 5] = s;
    __syncthreads();
    float tot = 0.f;
    #pragma unroll
    for (int i = 0; i < 8; i++) tot += red[i];
    float inv = rsqrtf(tot / (float)cols + 1e-6f);
    for (int c = tid; c < cols; c += 256)
        out[(size_t)row * cols + c] = __float2half_rn(xr[c] * inv * w[c]);
}

// ---------------- ldmatrix helpers ----------------
__device__ __forceinline__ void ldsm4(uint32_t& r0, uint32_t& r1, uint32_t& r2, uint32_t& r3,
                                      uint32_t addr) {
    asm volatile("ldmatrix.sync.aligned.m8n8.x4.shared.b16 {%0,%1,%2,%3}, [%4];"
                 : "=r"(r0), "=r"(r1), "=r"(r2), "=r"(r3) : "r"(addr));
}
__device__ __forceinline__ void ldsm4t(uint32_t& r0, uint32_t& r1, uint32_t& r2, uint32_t& r3,
                                       uint32_t addr) {
    asm volatile("ldmatrix.sync.aligned.m8n8.x4.trans.shared.b16 {%0,%1,%2,%3}, [%4];"
                 : "=r"(r0), "=r"(r1), "=r"(r2), "=r"(r3) : "r"(addr));
}
#define MMA16816(acc, a0, a1, a2, a3, b0, b1)                                   \
    asm volatile("mma.sync.aligned.m16n8k16.row.col.f32.f16.f16.f32 "           \
                 "{%0,%1,%2,%3}, {%4,%5,%6,%7}, {%8,%9}, {%0,%1,%2,%3};"        \
                 : "+f"((acc)[0]), "+f"((acc)[1]), "+f"((acc)[2]), "+f"((acc)[3]) \
                 : "r"(a0), "r"(a1), "r"(a2), "r"(a3), "r"(b0), "r"(b1))

__device__ __forceinline__ float silu_f(float x) {
    return x / (1.0f + __expf(-x));
}

// ---------------- FP16 mma.sync GEMM (fp32 acc), 3-stage, ldmatrix --------
// 256 threads = 8 warps (2m x 4n), warp tile 64x32, CTA tile 128x128.
// EPI: 0 = fp32 C              1 = fp32 C, C = acc + R(fp32)
//      2 = fp16 C              3 = fp16 C, C = silu(R(fp16)) * acc
#define HPITCH 40
#define HSTG  (128*HPITCH)
#define GEMM_SMEM (3*2*HSTG*2)
template<int EPI>
__global__ void __launch_bounds__(256, 2)
h16gemm(const __half* __restrict__ A, const __half* __restrict__ W,
        const void* __restrict__ Rv, void* __restrict__ Cv,
        int M, int N, int K) {
    extern __shared__ __half smh[];
    const uint32_t sbase = (uint32_t)__cvta_generic_to_shared(smh);

    const int tid  = threadIdx.x;
    const int warp = tid >> 5, lane = tid & 31;
    const int wm = warp >> 2;              // 0..1 -> 64 rows
    const int wn = warp & 3;               // 0..3 -> 32 cols
    const int g = lane >> 2, t = lane & 3;
    const int bm = blockIdx.y * 128;
    const int bn = blockIdx.x * 128;

    float acc[4][4][4];
    #pragma unroll
    for (int i = 0; i < 4; i++)
        #pragma unroll
        for (int j = 0; j < 4; j++)
            #pragma unroll
            for (int c = 0; c < 4; c++) acc[i][j][c] = 0.f;

    const int arow = wm * 64 + (lane & 15);
    const int acol = (lane >> 4) << 3;
    const int brow = wn * 32 + ((lane >> 4) << 3) + (lane & 7);
    const int bcol = ((lane >> 3) & 1) << 3;

    auto load_stage = [&](int s, int k0) {
        uint32_t sA = sbase + (uint32_t)(s * 2 * HSTG) * 2;
        uint32_t sW = sA + (uint32_t)HSTG * 2;
        #pragma unroll
        for (int i = 0; i < 2; i++) {
            int ch = tid + 256 * i;        // 0..511
            int m = ch >> 2, c8 = (ch & 3) * 8;
            uint32_t d = sA + (uint32_t)(m * HPITCH + c8) * 2;
            const __half* src = &A[(size_t)(bm + m) * K + k0 + c8];
            asm volatile("cp.async.cg.shared.global [%0], [%1], 16;" :: "r"(d), "l"(src));
            int n = bn + m;
            int ok = (n < N) ? 16 : 0;
            uint32_t dw = sW + (uint32_t)(m * HPITCH + c8) * 2;
            const __half* srcw = &W[(size_t)(n < N ? n : 0) * K + k0 + c8];
            asm volatile("cp.async.cg.shared.global [%0], [%1], 16, %2;"
                         :: "r"(dw), "l"(srcw), "r"(ok));
        }
        asm volatile("cp.async.commit_group;" ::: "memory");
    };

    auto compute = [&](int s) {
        uint32_t sA = sbase + (uint32_t)(s * 2 * HSTG) * 2;
        uint32_t sW = sA + (uint32_t)HSTG * 2;
        #pragma unroll
        for (int ks = 0; ks < 2; ks++) {
            int kk = ks * 16;
            uint32_t af[4][4];
            #pragma unroll
            for (int i = 0; i < 4; i++)
                ldsm4(af[i][0], af[i][1], af[i][2], af[i][3],
                      sA + (uint32_t)((arow + i * 16) * HPITCH + kk + acol) * 2);
            uint32_t bf[4][2];
            #pragma unroll
            for (int jj = 0; jj < 2; jj++)
                ldsm4(bf[2 * jj][0], bf[2 * jj][1], bf[2 * jj + 1][0], bf[2 * jj + 1][1],
                      sW + (uint32_t)((jj * 16 + brow) * HPITCH + kk + bcol) * 2);
            #pragma unroll
            for (int i = 0; i < 4; i++)
                #pragma unroll
                for (int j = 0; j < 4; j++)
                    MMA16816(acc[i][j], af[i][0], af[i][1], af[i][2], af[i][3],
                             bf[j][0], bf[j][1]);
        }
    };

    const int NK = K >> 5;
    load_stage(0, 0);
    load_stage(1, 32);

    for (int i = 0; i < NK; i++) {
        if (i + 1 < NK) asm volatile("cp.async.wait_group 1;" ::: "memory");
        else            asm volatile("cp.async.wait_group 0;" ::: "memory");
        __syncthreads();
        if (i + 2 < NK) load_stage((i + 2) % 3, (i + 2) * 32);
        compute(i % 3);
    }

    // ---- epilogue ----
    #pragma unroll
    for (int i = 0; i < 4; i++) {
        int r0 = bm + wm * 64 + i * 16 + g;
        #pragma unroll
        for (int j = 0; j < 4; j++) {
            int c = bn + wn * 32 + j * 8 + 2 * t;
            if (c < N) {
                #pragma unroll
                for (int half = 0; half < 2; half++) {
                    int rr = r0 + half * 8;
                    float a0 = acc[i][j][2 * half], a1 = acc[i][j][2 * half + 1];
                    size_t idx = (size_t)rr * N + c;
                    if (EPI == 0) {
                        *(float2*)&((float*)Cv)[idx] = make_float2(a0, a1);
                    } else if (EPI == 1) {
                        float2 r = *(const float2*)&((const float*)Rv)[idx];
                        *(float2*)&((float*)Cv)[idx] = make_float2(a0 + r.x, a1 + r.y);
                    } else if (EPI == 2) {
                        *(__half2*)&((__half*)Cv)[idx] = __floats2half2_rn(a0, a1);
                    } else {
                        __half2 gh2 = *(const __half2*)&((const __half*)Rv)[idx];
                        float g0 = __half2float(gh2.x), g1 = __half2float(gh2.y);
                        *(__half2*)&((__half*)Cv)[idx] =
                            __floats2half2_rn(silu_f(g0) * a0, silu_f(g1) * a1);
                    }
                }
            }
        }
    }
}

// ---------------- RoPE (yarn) helpers ----------------
__device__ __forceinline__ void yarn_cossin(int j, int pos, float& c, float& s) {
    float ar = (float)j * (1.0f / 32.0f);
    float fe = __powf(10000.0f, -ar);
    float fi = fe * (1.0f / 40.0f);
    float ramp = fminf(fmaxf(((float)j - 10.0f) * (1.0f / 13.0f), 0.0f), 1.0f);
    float f = fi * ramp + fe * (1.0f - ramp);
    float a = (float)pos * f;
    c = cosf(a); s = sinf(a);
}

// q fp16 [NTOK, NH*DQ] -> qf fp16 [B,H,S,DQ] with rope on last 64
__global__ void build_qf(const __half* __restrict__ q, const int* __restrict__ pos_ids,
                         __half* __restrict__ qf) {
    int t = blockIdx.x;
    int b = t / SEQ, s = t % SEQ;
    int tid = threadIdx.x;              // 128
    __shared__ float cs[32], sn[32];
    int pos = pos_ids[t];
    if (tid < 32) yarn_cossin(tid, pos, cs[tid], sn[tid]);
    __syncthreads();
    for (int h = 0; h < NH; h++) {
        size_t src = (size_t)t * (NH * DQ) + h * DQ;
        size_t dst = ((size_t)(b * NH + h) * SEQ + s) * DQ;
        qf[dst + tid] = q[src + tid];
        if (tid < 32) {
            float p0 = __half2float(q[src + DNOPE + 2 * tid]);
            float p1 = __half2float(q[src + DNOPE + 2 * tid + 1]);
            qf[dst + DNOPE + tid]      = __float2half_rn(p0 * cs[tid] - p1 * sn[tid]);
            qf[dst + DNOPE + 32 + tid] = __float2half_rn(p1 * cs[tid] + p0 * sn[tid]);
        }
    }
}

// kv fp16 [NTOK, NH*256], ckv fp32 -> kf fp16 [B,H,S,192], v fp16 [B,H,S,128]
__global__ void build_kf(const __half* __restrict__ kv, const float* __restrict__ ckv,
                         const int* __restrict__ pos_ids,
                         __half* __restrict__ kf, __half* __restrict__ vv) {
    int t = blockIdx.x;
    int b = t / SEQ, s = t % SEQ;
    int tid = threadIdx.x;              // 128
    __shared__ float cs[32], sn[32], kr[64];
    int pos = pos_ids[t];
    if (tid < 32) yarn_cossin(tid, pos, cs[tid], sn[tid]);
    __syncthreads();
    if (tid < 32) {
        float p0 = ckv[(size_t)t * (KVR + DROPE) + KVR + 2 * tid];
        float p1 = ckv[(size_t)t * (KVR + DROPE) + KVR + 2 * tid + 1];
        kr[tid]      = p0 * cs[tid] - p1 * sn[tid];
        kr[tid + 32] = p1 * cs[tid] + p0 * sn[tid];
    }
    __syncthreads();
    for (int h = 0; h < NH; h++) {
        size_t src = (size_t)t * (NH * 256) + h * 256;
        size_t d0 = ((size_t)(b * NH + h) * SEQ + s);
        kf[d0 * DQ + tid] = kv[src + tid];
        vv[d0 * DV + tid] = kv[src + DNOPE + tid];
        if (tid < 64) kf[d0 * DQ + DNOPE + tid] = __float2half_rn(kr[tid]);
    }
}

// ---------------- Tensor-core flash attention (single K/V buffer, 3 CTA/SM)
#define QPITCH 200
#define VPITCH 136
#define ATT_SMEM ((2*64*QPITCH + 64*VPITCH) * 2)
__global__ void __launch_bounds__(128)
attn_tc(const __half* __restrict__ qf, const __half* __restrict__ kf,
        const __half* __restrict__ vv, __half* __restrict__ out) {
    extern __shared__ __half sm[];
    const uint32_t sQ = (uint32_t)__cvta_generic_to_shared(sm);
    const uint32_t sK = sQ + 64 * QPITCH * 2;
    const uint32_t sV = sK + 64 * QPITCH * 2;
    const int tid = threadIdx.x, warp = tid >> 5, lane = tid & 31;
    const int g = lane >> 2, t = lane & 3;
    const int b = blockIdx.z, h = blockIdx.y;
    const int q0 = ((int)gridDim.x - 1 - (int)blockIdx.x) * 64;
    const __half* Qg = qf + (size_t)(b * NH + h) * SEQ * DQ;
    const __half* Kg = kf + (size_t)(b * NH + h) * SEQ * DQ;
    const __half* Vg = vv + (size_t)(b * NH + h) * SEQ * DV;
    const int wrow = warp * 16;
    const float scale = 0.07216878364870323f;    // 192^-0.5

    #pragma unroll
    for (int i = 0; i < 12; i++) {
        int ch = tid + 128 * i;
        int r = ch / 24, c = (ch % 24) * 8;
        uint32_t d = sQ + (uint32_t)(r * QPITCH + c) * 2;
        const __half* src = Qg + (size_t)(q0 + r) * DQ + c;
        asm volatile("cp.async.cg.shared.global [%0], [%1], 16;" :: "r"(d), "l"(src));
    }
    asm volatile("cp.async.commit_group;" ::: "memory");

    float o[16][4];
    #pragma unroll
    for (int i = 0; i < 16; i++)
        #pragma unroll
        for (int c = 0; c < 4; c++) o[i][c] = 0.f;
    float m0 = -INFINITY, m1 = -INFINITY, l0 = 0.f, l1 = 0.f;

    const uint32_t aoff = (uint32_t)((wrow + (lane & 15)) * QPITCH + ((lane >> 4) << 3)) * 2;
    const int brow = ((lane >> 4) << 3) + (lane & 7);
    const int bcol = ((lane >> 3) & 1) << 3;
    const int vrow = lane & 15;
    const int vcol = ((lane >> 4) << 3);

    for (int kc = 0; kc <= q0; kc += 64) {
        __syncthreads();
        #pragma unroll
        for (int i = 0; i < 12; i++) {
            int ch = tid + 128 * i;
            int r = ch / 24, c = (ch % 24) * 8;
            uint32_t d = sK + (uint32_t)(r * QPITCH + c) * 2;
            const __half* src = Kg + (size_t)(kc + r) * DQ + c;
            asm volatile("cp.async.cg.shared.global [%0], [%1], 16;" :: "r"(d), "l"(src));
        }
        #pragma unroll
        for (int i = 0; i < 8; i++) {
            int ch = tid + 128 * i;
            int r = ch / 16, c = (ch % 16) * 8;
            uint32_t d = sV + (uint32_t)(r * VPITCH + c) * 2;
            const __half* src = Vg + (size_t)(kc + r) * DV + c;
            asm volatile("cp.async.cg.shared.global [%0], [%1], 16;" :: "r"(d), "l"(src));
        }
        asm volatile("cp.async.commit_group;" ::: "memory");
        asm volatile("cp.async.wait_group 0;" ::: "memory");
        __syncthreads();

        // ---- S = Q @ K^T ----
        float sacc[8][4];
        #pragma unroll
        for (int nt = 0; nt < 8; nt++)
            #pragma unroll
            for (int c = 0; c < 4; c++) sacc[nt][c] = 0.f;
        #pragma unroll
        for (int kt = 0; kt < 12; kt++) {
            uint32_t a0, a1, a2, a3;
            ldsm4(a0, a1, a2, a3, sQ + aoff + kt * 32);
            uint32_t bf[8][2];
            #pragma unroll
            for (int jj = 0; jj < 4; jj++)
                ldsm4(bf[2 * jj][0], bf[2 * jj][1], bf[2 * jj + 1][0], bf[2 * jj + 1][1],
                      sK + (uint32_t)((jj * 16 + brow) * QPITCH + kt * 16 + bcol) * 2);
            #pragma unroll
            for (int nt = 0; nt < 8; nt++)
                MMA16816(sacc[nt], a0, a1, a2, a3, bf[nt][0], bf[nt][1]);
        }
        int r0w = q0 + wrow + g, r1w = r0w + 8;
        #pragma unroll
        for (int nt = 0; nt < 8; nt++)
            #pragma unroll
            for (int c = 0; c < 4; c++) sacc[nt][c] *= scale;
        if (kc == q0) {
            #pragma unroll
            for (int nt = 0; nt < 8; nt++) {
                int c0 = kc + nt * 8 + 2 * t;
                if (c0     > r0w) sacc[nt][0] = -INFINITY;
                if (c0 + 1 > r0w) sacc[nt][1] = -INFINITY;
                if (c0     > r1w) sacc[nt][2] = -INFINITY;
                if (c0 + 1 > r1w) sacc[nt][3] = -INFINITY;
            }
        }
        // ---- online softmax ----
        float mx0 = -INFINITY, mx1 = -INFINITY;
        #pragma unroll
        for (int nt = 0; nt < 8; nt++) {
            mx0 = fmaxf(mx0, fmaxf(sacc[nt][0], sacc[nt][1]));
            mx1 = fmaxf(mx1, fmaxf(sacc[nt][2], sacc[nt][3]));
        }
        mx0 = fmaxf(mx0, __shfl_xor_sync(0xffffffffu, mx0, 1));
        mx0 = fmaxf(mx0, __shfl_xor_sync(0xffffffffu, mx0, 2));
        mx1 = fmaxf(mx1, __shfl_xor_sync(0xffffffffu, mx1, 1));
        mx1 = fmaxf(mx1, __shfl_xor_sync(0xffffffffu, mx1, 2));
        float nm0 = fmaxf(m0, mx0), nm1 = fmaxf(m1, mx1);
        float cf0 = __expf(m0 - nm0), cf1 = __expf(m1 - nm1);
        float s0 = 0.f, s1 = 0.f;
        uint32_t ph01[8], ph23[8];
        #pragma unroll
        for (int nt = 0; nt < 8; nt++) {
            float p0 = __expf(sacc[nt][0] - nm0);
            float p1 = __expf(sacc[nt][1] - nm0);
            float p2 = __expf(sacc[nt][2] - nm1);
            float p3 = __expf(sacc[nt][3] - nm1);
            s0 += p0 + p1; s1 += p2 + p3;
            __half2 q01 = __floats2half2_rn(p0, p1);
            __half2 q23 = __floats2half2_rn(p2, p3);
            ph01[nt] = *(uint32_t*)&q01;
            ph23[nt] = *(uint32_t*)&q23;
        }
        s0 += __shfl_xor_sync(0xffffffffu, s0, 1);
        s0 += __shfl_xor_sync(0xffffffffu, s0, 2);
        s1 += __shfl_xor_sync(0xffffffffu, s1, 1);
        s1 += __shfl_xor_sync(0xffffffffu, s1, 2);
        l0 = l0 * cf0 + s0;
        l1 = l1 * cf1 + s1;
        m0 = nm0; m1 = nm1;
        #pragma unroll
        for (int nv = 0; nv < 16; nv++) {
            o[nv][0] *= cf0; o[nv][1] *= cf0;
            o[nv][2] *= cf1; o[nv][3] *= cf1;
        }
        // ---- O += P @ V ----
        #pragma unroll
        for (int kt2 = 0; kt2 < 4; kt2++) {
            uint32_t a0 = ph01[2 * kt2], a1 = ph23[2 * kt2];
            uint32_t a2 = ph01[2 * kt2 + 1], a3 = ph23[2 * kt2 + 1];
            #pragma unroll
            for (int jv = 0; jv < 8; jv++) {
                uint32_t b0, b1, b2, b3;
                ldsm4t(b0, b1, b2, b3,
                       sV + (uint32_t)((kt2 * 16 + vrow) * VPITCH + jv * 16 + vcol) * 2);
                MMA16816(o[2 * jv],     a0, a1, a2, a3, b0, b1);
                MMA16816(o[2 * jv + 1], a0, a1, a2, a3, b2, b3);
            }
        }
    }

    float inv0 = 1.f / l0, inv1 = 1.f / l1;
    int r0w = q0 + wrow + g, r1w = r0w + 8;
    #pragma unroll
    for (int nv = 0; nv < 16; nv++) {
        int col = nv * 8 + 2 * t;
        __half2 v0 = __floats2half2_rn(o[nv][0] * inv0, o[nv][1] * inv0);
        __half2 v1 = __floats2half2_rn(o[nv][2] * inv1, o[nv][3] * inv1);
        *(__half2*)&out[(size_t)(b * SEQ + r0w) * (NH * DV) + h * DV + col] = v0;
        *(__half2*)&out[(size_t)(b * SEQ + r1w) * (NH * DV) + h * DV + col] = v1;
    }
}

// ---------------- Launch ----------------
extern "C" void kernel_launch(void* const* d_in, const int* in_sizes, int n_in,
                              void* d_out, int out_size) {
    const float* hidden = (const float*)d_in[0];
    const int*   pos    = (const int*)d_in[1];
    const float* Wq     = (const float*)d_in[2];
    const float* Wkva   = (const float*)d_in[3];
    const float* w_kvln = (const float*)d_in[4];
    const float* Wkvb   = (const float*)d_in[5];
    const float* Wo     = (const float*)d_in[6];
    const float* Wg     = (const float*)d_in[7];
    const float* Wu     = (const float*)d_in[8];
    const float* Wd     = (const float*)d_in[9];
    const float* w_ln1  = (const float*)d_in[10];
    const float* w_ln2  = (const float*)d_in[11];
    float* out = (float*)d_out;

    __half *xln, *cln, *attn, *yh, *ggh, *gh, *qh, *kvh, *qfp, *kfp, *vp;
    __half *wq, *wkva, *wkvb, *wo, *wg, *wu, *wd;
    float *ckv, *x1;
    cudaGetSymbolAddress((void**)&xln,  h_xln);
    cudaGetSymbolAddress((void**)&cln,  h_cln);
    cudaGetSymbolAddress((void**)&attn, h_attn);
    cudaGetSymbolAddress((void**)&yh,   h_y);
    cudaGetSymbolAddress((void**)&ggh,  h_gg);
    cudaGetSymbolAddress((void**)&gh,   h_gh);
    cudaGetSymbolAddress((void**)&qh,   h_q);
    cudaGetSymbolAddress((void**)&kvh,  h_kv);
    cudaGetSymbolAddress((void**)&qfp,  h_qf);
    cudaGetSymbolAddress((void**)&kfp,  h_kf);
    cudaGetSymbolAddress((void**)&vp,   h_v);
    cudaGetSymbolAddress((void**)&wq,   hw_q);
    cudaGetSymbolAddress((void**)&wkva, hw_kva);
    cudaGetSymbolAddress((void**)&wkvb, hw_kvb);
    cudaGetSymbolAddress((void**)&wo,   hw_o);
    cudaGetSymbolAddress((void**)&wg,   hw_g);
    cudaGetSymbolAddress((void**)&wu,   hw_u);
    cudaGetSymbolAddress((void**)&wd,   hw_d);
    cudaGetSymbolAddress((void**)&ckv,  g_ckv);
    cudaGetSymbolAddress((void**)&x1,   g_x1);

    cudaFuncSetAttribute(h16gemm<0>, cudaFuncAttributeMaxDynamicSharedMemorySize, GEMM_SMEM);
    cudaFuncSetAttribute(h16gemm<1>, cudaFuncAttributeMaxDynamicSharedMemorySize, GEMM_SMEM);
    cudaFuncSetAttribute(h16gemm<2>, cudaFuncAttributeMaxDynamicSharedMemorySize, GEMM_SMEM);
    cudaFuncSetAttribute(h16gemm<3>, cudaFuncAttributeMaxDynamicSharedMemorySize, GEMM_SMEM);
    cudaFuncSetAttribute(attn_tc, cudaFuncAttributeMaxDynamicSharedMemorySize, ATT_SMEM);

    dim3 blk(256);
    auto cvt = [&](const float* s, __half* d, int n) {
        int n4 = n / 4;
        w2h_kernel<<<(n4 + 255) / 256, 256>>>(s, d, n4);
    };
    // launch order: #4 = Wq GEMM (profiled slot)
    cvt(Wq, wq, NH * DQ * HID);                                     // 1
    rmsnorm_kernel<<<NTOK, blk>>>(hidden, w_ln1, xln, HID, HID);    // 2
    cvt(Wkva, wkva, (KVR + DROPE) * HID);                           // 3
    // 4: q = xln @ Wq^T (fp16 out)  [4096 x 3072] K=2048
    h16gemm<2><<<dim3(24, 32), 256, GEMM_SMEM>>>(xln, wq, nullptr, qh, NTOK, NH * DQ, HID);
    // ckv = xln @ Wkva^T (fp32 out)
    h16gemm<0><<<dim3(5, 32), 256, GEMM_SMEM>>>(xln, wkva, nullptr, ckv, NTOK, KVR + DROPE, HID);
    rmsnorm_kernel<<<NTOK, blk>>>(ckv, w_kvln, cln, KVR, KVR + DROPE);
    cvt(Wkvb, wkvb, NH * (DNOPE + DV) * KVR);
    // kv = c_ln @ Wkvb^T (fp16 out)  K=512
    h16gemm<2><<<dim3(32, 32), 256, GEMM_SMEM>>>(cln, wkvb, nullptr, kvh, NTOK, NH * 256, KVR);
    build_qf<<<NTOK, 128>>>(qh, pos, qfp);
    build_kf<<<NTOK, 128>>>(kvh, ckv, pos, kfp, vp);
    // tensor-core flash attention
    attn_tc<<<dim3(SEQ / 64, NH, BATCH), 128, ATT_SMEM>>>(qfp, kfp, vp, attn);
    cvt(Wo, wo, HID * NH * DV);
    // x1 = hidden + attn @ Wo^T
    h16gemm<1><<<dim3(16, 32), 256, GEMM_SMEM>>>(attn, wo, hidden, x1, NTOK, HID, NH * DV);
    rmsnorm_kernel<<<NTOK, blk>>>(x1, w_ln2, yh, HID, HID);
    cvt(Wg, wg, INTER * HID);
    cvt(Wu, wu, INTER * HID);
    cvt(Wd, wd, HID * INTER);
    // g = y @ Wg^T (fp16 out)
    h16gemm<2><<<dim3(86, 32), 256, GEMM_SMEM>>>(yh, wg, nullptr, ggh, NTOK, INTER, HID);
    // gh = silu(g) * (y @ Wu^T)  (fused epilogue, fp16 out)
    h16gemm<3><<<dim3(86, 32), 256, GEMM_SMEM>>>(yh, wu, ggh, gh, NTOK, INTER, HID);
    // out = x1 + gh @ Wd^T  K=10944
    h16gemm<1><<<dim3(16, 32), 256, GEMM_SMEM>>>(gh, wd, x1, out, NTOK, HID, INTER);
}

// round 14
// speedup vs baseline: 1.0342x; 1.0342x over previous
#include <cuda_runtime.h>
#include <cuda_fp16.h>
#include <math.h>
#include <stdint.h>

// ---------------- Problem constants (fixed shapes) ----------------
#define BATCH 2
#define SEQ   2048
#define NTOK  (BATCH*SEQ)        // 4096
#define HID   2048
#define NH    16
#define DQ    192
#define DNOPE 128
#define DROPE 64
#define DV    128
#define KVR   512
#define INTER 10944

// ---------------- Scratch (device globals; allocation-free) ----------------
__device__ __half h_xln [NTOK*HID];
__device__ __half h_cln [NTOK*KVR];
__device__ __half h_attn[NTOK*HID];
__device__ __half h_y   [NTOK*HID];
__device__ __half h_gg  [NTOK*INTER];
__device__ __half h_gh  [NTOK*INTER];
__device__ __half h_q   [NTOK*NH*DQ];
__device__ __half h_kv  [NTOK*NH*(DNOPE+DV)];
__device__ __half h_qf  [BATCH*NH*SEQ*DQ];
__device__ __half h_kf  [BATCH*NH*SEQ*DQ];
__device__ __half h_v   [BATCH*NH*SEQ*DV];
__device__ float g_ckv [NTOK*(KVR+DROPE)];
__device__ float g_x1  [NTOK*HID];
// fp16 weight copies
__device__ __half hw_q  [NH*DQ*HID];
__device__ __half hw_kva[(KVR+DROPE)*HID];
__device__ __half hw_kvb[NH*(DNOPE+DV)*KVR];
__device__ __half hw_o  [HID*NH*DV];
__device__ __half hw_g  [INTER*HID];
__device__ __half hw_u  [INTER*HID];
__device__ __half hw_d  [HID*INTER];

// ---------------- weight fp32 -> fp16 ----------------
__global__ void w2h_kernel(const float* __restrict__ in, __half* __restrict__ out, int n4) {
    int i = blockIdx.x * blockDim.x + threadIdx.x;
    if (i < n4) {
        float4 v = ((const float4*)in)[i];
        __half2 h0 = __floats2half2_rn(v.x, v.y);
        __half2 h1 = __floats2half2_rn(v.z, v.w);
        ((uint2*)out)[i] = make_uint2(*(uint32_t*)&h0, *(uint32_t*)&h1);
    }
}

// ---------------- RMSNorm (fp32 in, fp16 out) ----------------
__global__ void rmsnorm_kernel(const float* __restrict__ in, const float* __restrict__ w,
                               __half* __restrict__ out, int cols, int instride) {
    int row = blockIdx.x;
    int tid = threadIdx.x;
    const float* xr = in + (size_t)row * instride;
    float s = 0.f;
    for (int c = tid; c < cols; c += 256) { float v = xr[c]; s += v * v; }
    __shared__ float red[8];
    for (int o = 16; o; o >>= 1) s += __shfl_xor_sync(0xffffffffu, s, o);
    if ((tid & 31) == 0) red[tid >> 5] = s;
    __syncthreads();
    float tot = 0.f;
    #pragma unroll
    for (int i = 0; i < 8; i++) tot += red[i];
    float inv = rsqrtf(tot / (float)cols + 1e-6f);
    for (int c = tid; c < cols; c += 256)
        out[(size_t)row * cols + c] = __float2half_rn(xr[c] * inv * w[c]);
}

// ---------------- ldmatrix helpers ----------------
__device__ __forceinline__ void ldsm4(uint32_t& r0, uint32_t& r1, uint32_t& r2, uint32_t& r3,
                                      uint32_t addr) {
    asm volatile("ldmatrix.sync.aligned.m8n8.x4.shared.b16 {%0,%1,%2,%3}, [%4];"
                 : "=r"(r0), "=r"(r1), "=r"(r2), "=r"(r3) : "r"(addr));
}
__device__ __forceinline__ void ldsm4t(uint32_t& r0, uint32_t& r1, uint32_t& r2, uint32_t& r3,
                                       uint32_t addr) {
    asm volatile("ldmatrix.sync.aligned.m8n8.x4.trans.shared.b16 {%0,%1,%2,%3}, [%4];"
                 : "=r"(r0), "=r"(r1), "=r"(r2), "=r"(r3) : "r"(addr));
}
#define MMA16816(acc, a0, a1, a2, a3, b0, b1)                                   \
    asm volatile("mma.sync.aligned.m16n8k16.row.col.f32.f16.f16.f32 "           \
                 "{%0,%1,%2,%3}, {%4,%5,%6,%7}, {%8,%9}, {%0,%1,%2,%3};"        \
                 : "+f"((acc)[0]), "+f"((acc)[1]), "+f"((acc)[2]), "+f"((acc)[3]) \
                 : "r"(a0), "r"(a1), "r"(a2), "r"(a3), "r"(b0), "r"(b1))

__device__ __forceinline__ float silu_f(float x) {
    return x / (1.0f + __expf(-x));
}

// ---------------- FP16 mma.sync GEMM (fp32 acc), 3-stage, ldmatrix --------
// 128 threads = 4 warps (2m x 2n), warp tile 64x64, CTA tile 128x128.
// __launch_bounds__(128,3): regs capped ~170 -> 3 CTAs/SM (12 warps).
// EPI: 0 = fp32 C              1 = fp32 C, C = acc + R(fp32)
//      2 = fp16 C              3 = fp16 C, C = silu(R(fp16)) * acc
#define HPITCH 40
#define HSTG  (128*HPITCH)
#define GEMM_SMEM (3*2*HSTG*2)
template<int EPI>
__global__ void __launch_bounds__(128, 3)
h16gemm(const __half* __restrict__ A, const __half* __restrict__ W,
        const void* __restrict__ Rv, void* __restrict__ Cv,
        int M, int N, int K) {
    extern __shared__ __half smh[];
    const uint32_t sbase = (uint32_t)__cvta_generic_to_shared(smh);

    const int tid  = threadIdx.x;
    const int warp = tid >> 5, lane = tid & 31;
    const int wm = warp >> 1;              // 0..1 -> 64 rows
    const int wn = warp & 1;               // 0..1 -> 64 cols
    const int g = lane >> 2, t = lane & 3;
    const int bm = blockIdx.y * 128;
    const int bn = blockIdx.x * 128;

    float acc[4][8][4];
    #pragma unroll
    for (int i = 0; i < 4; i++)
        #pragma unroll
        for (int j = 0; j < 8; j++)
            #pragma unroll
            for (int c = 0; c < 4; c++) acc[i][j][c] = 0.f;

    const int arow = wm * 64 + (lane & 15);
    const int acol = (lane >> 4) << 3;
    const int brow = wn * 64 + ((lane >> 4) << 3) + (lane & 7);
    const int bcol = ((lane >> 3) & 1) << 3;

    auto load_stage = [&](int s, int k0) {
        uint32_t sA = sbase + (uint32_t)(s * 2 * HSTG) * 2;
        uint32_t sW = sA + (uint32_t)HSTG * 2;
        #pragma unroll
        for (int i = 0; i < 4; i++) {
            int ch = tid + 128 * i;
            int m = ch >> 2, c8 = (ch & 3) * 8;
            uint32_t d = sA + (uint32_t)(m * HPITCH + c8) * 2;
            const __half* src = &A[(size_t)(bm + m) * K + k0 + c8];
            asm volatile("cp.async.cg.shared.global [%0], [%1], 16;" :: "r"(d), "l"(src));
            int n = bn + m;
            int ok = (n < N) ? 16 : 0;
            uint32_t dw = sW + (uint32_t)(m * HPITCH + c8) * 2;
            const __half* srcw = &W[(size_t)(n < N ? n : 0) * K + k0 + c8];
            asm volatile("cp.async.cg.shared.global [%0], [%1], 16, %2;"
                         :: "r"(dw), "l"(srcw), "r"(ok));
        }
        asm volatile("cp.async.commit_group;" ::: "memory");
    };

    auto compute = [&](int s) {
        uint32_t sA = sbase + (uint32_t)(s * 2 * HSTG) * 2;
        uint32_t sW = sA + (uint32_t)HSTG * 2;
        #pragma unroll
        for (int ks = 0; ks < 2; ks++) {
            int kk = ks * 16;
            uint32_t af[4][4];
            #pragma unroll
            for (int i = 0; i < 4; i++)
                ldsm4(af[i][0], af[i][1], af[i][2], af[i][3],
                      sA + (uint32_t)((arow + i * 16) * HPITCH + kk + acol) * 2);
            uint32_t bf[8][2];
            #pragma unroll
            for (int jj = 0; jj < 4; jj++)
                ldsm4(bf[2 * jj][0], bf[2 * jj][1], bf[2 * jj + 1][0], bf[2 * jj + 1][1],
                      sW + (uint32_t)((jj * 16 + brow) * HPITCH + kk + bcol) * 2);
            #pragma unroll
            for (int i = 0; i < 4; i++)
                #pragma unroll
                for (int j = 0; j < 8; j++)
                    MMA16816(acc[i][j], af[i][0], af[i][1], af[i][2], af[i][3],
                             bf[j][0], bf[j][1]);
        }
    };

    const int NK = K >> 5;
    load_stage(0, 0);
    load_stage(1, 32);

    for (int i = 0; i < NK; i++) {
        if (i + 1 < NK) asm volatile("cp.async.wait_group 1;" ::: "memory");
        else            asm volatile("cp.async.wait_group 0;" ::: "memory");
        __syncthreads();
        if (i + 2 < NK) load_stage((i + 2) % 3, (i + 2) * 32);
        compute(i % 3);
    }

    // ---- epilogue ----
    #pragma unroll
    for (int i = 0; i < 4; i++) {
        int r0 = bm + wm * 64 + i * 16 + g;
        #pragma unroll
        for (int j = 0; j < 8; j++) {
            int c = bn + wn * 64 + j * 8 + 2 * t;
            if (c < N) {
                #pragma unroll
                for (int half = 0; half < 2; half++) {
                    int rr = r0 + half * 8;
                    float a0 = acc[i][j][2 * half], a1 = acc[i][j][2 * half + 1];
                    size_t idx = (size_t)rr * N + c;
                    if (EPI == 0) {
                        *(float2*)&((float*)Cv)[idx] = make_float2(a0, a1);
                    } else if (EPI == 1) {
                        float2 r = *(const float2*)&((const float*)Rv)[idx];
                        *(float2*)&((float*)Cv)[idx] = make_float2(a0 + r.x, a1 + r.y);
                    } else if (EPI == 2) {
                        *(__half2*)&((__half*)Cv)[idx] = __floats2half2_rn(a0, a1);
                    } else {
                        __half2 gh2 = *(const __half2*)&((const __half*)Rv)[idx];
                        float g0 = __half2float(gh2.x), g1 = __half2float(gh2.y);
                        *(__half2*)&((__half*)Cv)[idx] =
                            __floats2half2_rn(silu_f(g0) * a0, silu_f(g1) * a1);
                    }
                }
            }
        }
    }
}

// ---------------- RoPE (yarn) helpers ----------------
__device__ __forceinline__ void yarn_cossin(int j, int pos, float& c, float& s) {
    float ar = (float)j * (1.0f / 32.0f);
    float fe = __powf(10000.0f, -ar);
    float fi = fe * (1.0f / 40.0f);
    float ramp = fminf(fmaxf(((float)j - 10.0f) * (1.0f / 13.0f), 0.0f), 1.0f);
    float f = fi * ramp + fe * (1.0f - ramp);
    float a = (float)pos * f;
    c = cosf(a); s = sinf(a);
}

// q fp16 [NTOK, NH*DQ] -> qf fp16 [B,H,S,DQ] with rope on last 64
__global__ void build_qf(const __half* __restrict__ q, const int* __restrict__ pos_ids,
                         __half* __restrict__ qf) {
    int t = blockIdx.x;
    int b = t / SEQ, s = t % SEQ;
    int tid = threadIdx.x;              // 128
    __shared__ float cs[32], sn[32];
    int pos = pos_ids[t];
    if (tid < 32) yarn_cossin(tid, pos, cs[tid], sn[tid]);
    __syncthreads();
    for (int h = 0; h < NH; h++) {
        size_t src = (size_t)t * (NH * DQ) + h * DQ;
        size_t dst = ((size_t)(b * NH + h) * SEQ + s) * DQ;
        qf[dst + tid] = q[src + tid];
        if (tid < 32) {
            float p0 = __half2float(q[src + DNOPE + 2 * tid]);
            float p1 = __half2float(q[src + DNOPE + 2 * tid + 1]);
            qf[dst + DNOPE + tid]      = __float2half_rn(p0 * cs[tid] - p1 * sn[tid]);
            qf[dst + DNOPE + 32 + tid] = __float2half_rn(p1 * cs[tid] + p0 * sn[tid]);
        }
    }
}

// kv fp16 [NTOK, NH*256], ckv fp32 -> kf fp16 [B,H,S,192], v fp16 [B,H,S,128]
__global__ void build_kf(const __half* __restrict__ kv, const float* __restrict__ ckv,
                         const int* __restrict__ pos_ids,
                         __half* __restrict__ kf, __half* __restrict__ vv) {
    int t = blockIdx.x;
    int b = t / SEQ, s = t % SEQ;
    int tid = threadIdx.x;              // 128
    __shared__ float cs[32], sn[32], kr[64];
    int pos = pos_ids[t];
    if (tid < 32) yarn_cossin(tid, pos, cs[tid], sn[tid]);
    __syncthreads();
    if (tid < 32) {
        float p0 = ckv[(size_t)t * (KVR + DROPE) + KVR + 2 * tid];
        float p1 = ckv[(size_t)t * (KVR + DROPE) + KVR + 2 * tid + 1];
        kr[tid]      = p0 * cs[tid] - p1 * sn[tid];
        kr[tid + 32] = p1 * cs[tid] + p0 * sn[tid];
    }
    __syncthreads();
    for (int h = 0; h < NH; h++) {
        size_t src = (size_t)t * (NH * 256) + h * 256;
        size_t d0 = ((size_t)(b * NH + h) * SEQ + s);
        kf[d0 * DQ + tid] = kv[src + tid];
        vv[d0 * DV + tid] = kv[src + DNOPE + tid];
        if (tid < 64) kf[d0 * DQ + DNOPE + tid] = __float2half_rn(kr[tid]);
    }
}

// ---------------- Tensor-core flash attention (single K/V buffer, 3 CTA/SM)
#define QPITCH 200
#define VPITCH 136
#define ATT_SMEM ((2*64*QPITCH + 64*VPITCH) * 2)
__global__ void __launch_bounds__(128)
attn_tc(const __half* __restrict__ qf, const __half* __restrict__ kf,
        const __half* __restrict__ vv, __half* __restrict__ out) {
    extern __shared__ __half sm[];
    const uint32_t sQ = (uint32_t)__cvta_generic_to_shared(sm);
    const uint32_t sK = sQ + 64 * QPITCH * 2;
    const uint32_t sV = sK + 64 * QPITCH * 2;
    const int tid = threadIdx.x, warp = tid >> 5, lane = tid & 31;
    const int g = lane >> 2, t = lane & 3;
    const int b = blockIdx.z, h = blockIdx.y;
    const int q0 = ((int)gridDim.x - 1 - (int)blockIdx.x) * 64;
    const __half* Qg = qf + (size_t)(b * NH + h) * SEQ * DQ;
    const __half* Kg = kf + (size_t)(b * NH + h) * SEQ * DQ;
    const __half* Vg = vv + (size_t)(b * NH + h) * SEQ * DV;
    const int wrow = warp * 16;
    const float scale = 0.07216878364870323f;    // 192^-0.5

    #pragma unroll
    for (int i = 0; i < 12; i++) {
        int ch = tid + 128 * i;
        int r = ch / 24, c = (ch % 24) * 8;
        uint32_t d = sQ + (uint32_t)(r * QPITCH + c) * 2;
        const __half* src = Qg + (size_t)(q0 + r) * DQ + c;
        asm volatile("cp.async.cg.shared.global [%0], [%1], 16;" :: "r"(d), "l"(src));
    }
    asm volatile("cp.async.commit_group;" ::: "memory");

    float o[16][4];
    #pragma unroll
    for (int i = 0; i < 16; i++)
        #pragma unroll
        for (int c = 0; c < 4; c++) o[i][c] = 0.f;
    float m0 = -INFINITY, m1 = -INFINITY, l0 = 0.f, l1 = 0.f;

    const uint32_t aoff = (uint32_t)((wrow + (lane & 15)) * QPITCH + ((lane >> 4) << 3)) * 2;
    const int brow = ((lane >> 4) << 3) + (lane & 7);
    const int bcol = ((lane >> 3) & 1) << 3;
    const int vrow = lane & 15;
    const int vcol = ((lane >> 4) << 3);

    for (int kc = 0; kc <= q0; kc += 64) {
        __syncthreads();
        #pragma unroll
        for (int i = 0; i < 12; i++) {
            int ch = tid + 128 * i;
            int r = ch / 24, c = (ch % 24) * 8;
            uint32_t d = sK + (uint32_t)(r * QPITCH + c) * 2;
            const __half* src = Kg + (size_t)(kc + r) * DQ + c;
            asm volatile("cp.async.cg.shared.global [%0], [%1], 16;" :: "r"(d), "l"(src));
        }
        #pragma unroll
        for (int i = 0; i < 8; i++) {
            int ch = tid + 128 * i;
            int r = ch / 16, c = (ch % 16) * 8;
            uint32_t d = sV + (uint32_t)(r * VPITCH + c) * 2;
            const __half* src = Vg + (size_t)(kc + r) * DV + c;
            asm volatile("cp.async.cg.shared.global [%0], [%1], 16;" :: "r"(d), "l"(src));
        }
        asm volatile("cp.async.commit_group;" ::: "memory");
        asm volatile("cp.async.wait_group 0;" ::: "memory");
        __syncthreads();

        // ---- S = Q @ K^T ----
        float sacc[8][4];
        #pragma unroll
        for (int nt = 0; nt < 8; nt++)
            #pragma unroll
            for (int c = 0; c < 4; c++) sacc[nt][c] = 0.f;
        #pragma unroll
        for (int kt = 0; kt < 12; kt++) {
            uint32_t a0, a1, a2, a3;
            ldsm4(a0, a1, a2, a3, sQ + aoff + kt * 32);
            uint32_t bf[8][2];
            #pragma unroll
            for (int jj = 0; jj < 4; jj++)
                ldsm4(bf[2 * jj][0], bf[2 * jj][1], bf[2 * jj + 1][0], bf[2 * jj + 1][1],
                      sK + (uint32_t)((jj * 16 + brow) * QPITCH + kt * 16 + bcol) * 2);
            #pragma unroll
            for (int nt = 0; nt < 8; nt++)
                MMA16816(sacc[nt], a0, a1, a2, a3, bf[nt][0], bf[nt][1]);
        }
        int r0w = q0 + wrow + g, r1w = r0w + 8;
        #pragma unroll
        for (int nt = 0; nt < 8; nt++)
            #pragma unroll
            for (int c = 0; c < 4; c++) sacc[nt][c] *= scale;
        if (kc == q0) {
            #pragma unroll
            for (int nt = 0; nt < 8; nt++) {
                int c0 = kc + nt * 8 + 2 * t;
                if (c0     > r0w) sacc[nt][0] = -INFINITY;
                if (c0 + 1 > r0w) sacc[nt][1] = -INFINITY;
                if (c0     > r1w) sacc[nt][2] = -INFINITY;
                if (c0 + 1 > r1w) sacc[nt][3] = -INFINITY;
            }
        }
        // ---- online softmax ----
        float mx0 = -INFINITY, mx1 = -INFINITY;
        #pragma unroll
        for (int nt = 0; nt < 8; nt++) {
            mx0 = fmaxf(mx0, fmaxf(sacc[nt][0], sacc[nt][1]));
            mx1 = fmaxf(mx1, fmaxf(sacc[nt][2], sacc[nt][3]));
        }
        mx0 = fmaxf(mx0, __shfl_xor_sync(0xffffffffu, mx0, 1));
        mx0 = fmaxf(mx0, __shfl_xor_sync(0xffffffffu, mx0, 2));
        mx1 = fmaxf(mx1, __shfl_xor_sync(0xffffffffu, mx1, 1));
        mx1 = fmaxf(mx1, __shfl_xor_sync(0xffffffffu, mx1, 2));
        float nm0 = fmaxf(m0, mx0), nm1 = fmaxf(m1, mx1);
        float cf0 = __expf(m0 - nm0), cf1 = __expf(m1 - nm1);
        float s0 = 0.f, s1 = 0.f;
        uint32_t ph01[8], ph23[8];
        #pragma unroll
        for (int nt = 0; nt < 8; nt++) {
            float p0 = __expf(sacc[nt][0] - nm0);
            float p1 = __expf(sacc[nt][1] - nm0);
            float p2 = __expf(sacc[nt][2] - nm1);
            float p3 = __expf(sacc[nt][3] - nm1);
            s0 += p0 + p1; s1 += p2 + p3;
            __half2 q01 = __floats2half2_rn(p0, p1);
            __half2 q23 = __floats2half2_rn(p2, p3);
            ph01[nt] = *(uint32_t*)&q01;
            ph23[nt] = *(uint32_t*)&q23;
        }
        s0 += __shfl_xor_sync(0xffffffffu, s0, 1);
        s0 += __shfl_xor_sync(0xffffffffu, s0, 2);
        s1 += __shfl_xor_sync(0xffffffffu, s1, 1);
        s1 += __shfl_xor_sync(0xffffffffu, s1, 2);
        l0 = l0 * cf0 + s0;
        l1 = l1 * cf1 + s1;
        m0 = nm0; m1 = nm1;
        #pragma unroll
        for (int nv = 0; nv < 16; nv++) {
            o[nv][0] *= cf0; o[nv][1] *= cf0;
            o[nv][2] *= cf1; o[nv][3] *= cf1;
        }
        // ---- O += P @ V ----
        #pragma unroll
        for (int kt2 = 0; kt2 < 4; kt2++) {
            uint32_t a0 = ph01[2 * kt2], a1 = ph23[2 * kt2];
            uint32_t a2 = ph01[2 * kt2 + 1], a3 = ph23[2 * kt2 + 1];
            #pragma unroll
            for (int jv = 0; jv < 8; jv++) {
                uint32_t b0, b1, b2, b3;
                ldsm4t(b0, b1, b2, b3,
                       sV + (uint32_t)((kt2 * 16 + vrow) * VPITCH + jv * 16 + vcol) * 2);
                MMA16816(o[2 * jv],     a0, a1, a2, a3, b0, b1);
                MMA16816(o[2 * jv + 1], a0, a1, a2, a3, b2, b3);
            }
        }
    }

    float inv0 = 1.f / l0, inv1 = 1.f / l1;
    int r0w = q0 + wrow + g, r1w = r0w + 8;
    #pragma unroll
    for (int nv = 0; nv < 16; nv++) {
        int col = nv * 8 + 2 * t;
        __half2 v0 = __floats2half2_rn(o[nv][0] * inv0, o[nv][1] * inv0);
        __half2 v1 = __floats2half2_rn(o[nv][2] * inv1, o[nv][3] * inv1);
        *(__half2*)&out[(size_t)(b * SEQ + r0w) * (NH * DV) + h * DV + col] = v0;
        *(__half2*)&out[(size_t)(b * SEQ + r1w) * (NH * DV) + h * DV + col] = v1;
    }
}

// ---------------- Launch ----------------
extern "C" void kernel_launch(void* const* d_in, const int* in_sizes, int n_in,
                              void* d_out, int out_size) {
    const float* hidden = (const float*)d_in[0];
    const int*   pos    = (const int*)d_in[1];
    const float* Wq     = (const float*)d_in[2];
    const float* Wkva   = (const float*)d_in[3];
    const float* w_kvln = (const float*)d_in[4];
    const float* Wkvb   = (const float*)d_in[5];
    const float* Wo     = (const float*)d_in[6];
    const float* Wg     = (const float*)d_in[7];
    const float* Wu     = (const float*)d_in[8];
    const float* Wd     = (const float*)d_in[9];
    const float* w_ln1  = (const float*)d_in[10];
    const float* w_ln2  = (const float*)d_in[11];
    float* out = (float*)d_out;

    __half *xln, *cln, *attn, *yh, *ggh, *gh, *qh, *kvh, *qfp, *kfp, *vp;
    __half *wq, *wkva, *wkvb, *wo, *wg, *wu, *wd;
    float *ckv, *x1;
    cudaGetSymbolAddress((void**)&xln,  h_xln);
    cudaGetSymbolAddress((void**)&cln,  h_cln);
    cudaGetSymbolAddress((void**)&attn, h_attn);
    cudaGetSymbolAddress((void**)&yh,   h_y);
    cudaGetSymbolAddress((void**)&ggh,  h_gg);
    cudaGetSymbolAddress((void**)&gh,   h_gh);
    cudaGetSymbolAddress((void**)&qh,   h_q);
    cudaGetSymbolAddress((void**)&kvh,  h_kv);
    cudaGetSymbolAddress((void**)&qfp,  h_qf);
    cudaGetSymbolAddress((void**)&kfp,  h_kf);
    cudaGetSymbolAddress((void**)&vp,   h_v);
    cudaGetSymbolAddress((void**)&wq,   hw_q);
    cudaGetSymbolAddress((void**)&wkva, hw_kva);
    cudaGetSymbolAddress((void**)&wkvb, hw_kvb);
    cudaGetSymbolAddress((void**)&wo,   hw_o);
    cudaGetSymbolAddress((void**)&wg,   hw_g);
    cudaGetSymbolAddress((void**)&wu,   hw_u);
    cudaGetSymbolAddress((void**)&wd,   hw_d);
    cudaGetSymbolAddress((void**)&ckv,  g_ckv);
    cudaGetSymbolAddress((void**)&x1,   g_x1);

    cudaFuncSetAttribute(h16gemm<0>, cudaFuncAttributeMaxDynamicSharedMemorySize, GEMM_SMEM);
    cudaFuncSetAttribute(h16gemm<1>, cudaFuncAttributeMaxDynamicSharedMemorySize, GEMM_SMEM);
    cudaFuncSetAttribute(h16gemm<2>, cudaFuncAttributeMaxDynamicSharedMemorySize, GEMM_SMEM);
    cudaFuncSetAttribute(h16gemm<3>, cudaFuncAttributeMaxDynamicSharedMemorySize, GEMM_SMEM);
    cudaFuncSetAttribute(attn_tc, cudaFuncAttributeMaxDynamicSharedMemorySize, ATT_SMEM);

    dim3 blk(256);
    auto cvt = [&](const float* s, __half* d, int n) {
        int n4 = n / 4;
        w2h_kernel<<<(n4 + 255) / 256, 256>>>(s, d, n4);
    };
    // launch order: #4 = Wq GEMM (profiled slot)
    cvt(Wq, wq, NH * DQ * HID);                                     // 1
    rmsnorm_kernel<<<NTOK, blk>>>(hidden, w_ln1, xln, HID, HID);    // 2
    cvt(Wkva, wkva, (KVR + DROPE) * HID);                           // 3
    // 4: q = xln @ Wq^T (fp16 out)  [4096 x 3072] K=2048
    h16gemm<2><<<dim3(24, 32), 128, GEMM_SMEM>>>(xln, wq, nullptr, qh, NTOK, NH * DQ, HID);
    // ckv = xln @ Wkva^T (fp32 out)
    h16gemm<0><<<dim3(5, 32), 128, GEMM_SMEM>>>(xln, wkva, nullptr, ckv, NTOK, KVR + DROPE, HID);
    rmsnorm_kernel<<<NTOK, blk>>>(ckv, w_kvln, cln, KVR, KVR + DROPE);
    cvt(Wkvb, wkvb, NH * (DNOPE + DV) * KVR);
    // kv = c_ln @ Wkvb^T (fp16 out)  K=512
    h16gemm<2><<<dim3(32, 32), 128, GEMM_SMEM>>>(cln, wkvb, nullptr, kvh, NTOK, NH * 256, KVR);
    build_qf<<<NTOK, 128>>>(qh, pos, qfp);
    build_kf<<<NTOK, 128>>>(kvh, ckv, pos, kfp, vp);
    // tensor-core flash attention
    attn_tc<<<dim3(SEQ / 64, NH, BATCH), 128, ATT_SMEM>>>(qfp, kfp, vp, attn);
    cvt(Wo, wo, HID * NH * DV);
    // x1 = hidden + attn @ Wo^T
    h16gemm<1><<<dim3(16, 32), 128, GEMM_SMEM>>>(attn, wo, hidden, x1, NTOK, HID, NH * DV);
    rmsnorm_kernel<<<NTOK, blk>>>(x1, w_ln2, yh, HID, HID);
    cvt(Wg, wg, INTER * HID);
    cvt(Wu, wu, INTER * HID);
    cvt(Wd, wd, HID * INTER);
    // g = y @ Wg^T (fp16 out)
    h16gemm<2><<<dim3(86, 32), 128, GEMM_SMEM>>>(yh, wg, nullptr, ggh, NTOK, INTER, HID);
    // gh = silu(g) * (y @ Wu^T)  (fused epilogue, fp16 out)
    h16gemm<3><<<dim3(86, 32), 128, GEMM_SMEM>>>(yh, wu, ggh, gh, NTOK, INTER, HID);
    // out = x1 + gh @ Wd^T  K=10944
    h16gemm<1><<<dim3(16, 32), 128, GEMM_SMEM>>>(gh, wd, x1, out, NTOK, HID, INTER);
}

// round 15
// speedup vs baseline: 1.1088x; 1.0721x over previous
#include <cuda_runtime.h>
#include <cuda_fp16.h>
#include <math.h>
#include <stdint.h>

// ---------------- Problem constants (fixed shapes) ----------------
#define BATCH 2
#define SEQ   2048
#define NTOK  (BATCH*SEQ)        // 4096
#define HID   2048
#define NH    16
#define DQ    192
#define DNOPE 128
#define DROPE 64
#define DV    128
#define KVR   512
#define INTER 10944

// ---------------- Scratch (device globals; allocation-free) ----------------
__device__ __half h_xln [NTOK*HID];
__device__ __half h_cln [NTOK*KVR];
__device__ __half h_attn[NTOK*HID];
__device__ __half h_y   [NTOK*HID];
__device__ __half h_gg  [NTOK*INTER];
__device__ __half h_gh  [NTOK*INTER];
__device__ __half h_q   [NTOK*NH*DQ];
__device__ __half h_kv  [NTOK*NH*(DNOPE+DV)];
__device__ __half h_qf  [BATCH*NH*SEQ*DQ];
__device__ __half h_kf  [BATCH*NH*SEQ*DQ];
__device__ __half h_v   [BATCH*NH*SEQ*DV];
__device__ float g_ckv [NTOK*(KVR+DROPE)];
__device__ float g_x1  [NTOK*HID];
// fp16 weight copies
__device__ __half hw_q  [NH*DQ*HID];
__device__ __half hw_kva[(KVR+DROPE)*HID];
__device__ __half hw_kvb[NH*(DNOPE+DV)*KVR];
__device__ __half hw_o  [HID*NH*DV];
__device__ __half hw_g  [INTER*HID];
__device__ __half hw_u  [INTER*HID];
__device__ __half hw_d  [HID*INTER];

// ---------------- weight fp32 -> fp16 ----------------
__global__ void w2h_kernel(const float* __restrict__ in, __half* __restrict__ out, int n4) {
    int i = blockIdx.x * blockDim.x + threadIdx.x;
    if (i < n4) {
        float4 v = ((const float4*)in)[i];
        __half2 h0 = __floats2half2_rn(v.x, v.y);
        __half2 h1 = __floats2half2_rn(v.z, v.w);
        ((uint2*)out)[i] = make_uint2(*(uint32_t*)&h0, *(uint32_t*)&h1);
    }
}

// ---------------- RMSNorm (fp32 in, fp16 out) ----------------
__global__ void rmsnorm_kernel(const float* __restrict__ in, const float* __restrict__ w,
                               __half* __restrict__ out, int cols, int instride) {
    int row = blockIdx.x;
    int tid = threadIdx.x;
    const float* xr = in + (size_t)row * instride;
    float s = 0.f;
    for (int c = tid; c < cols; c += 256) { float v = xr[c]; s += v * v; }
    __shared__ float red[8];
    for (int o = 16; o; o >>= 1) s += __shfl_xor_sync(0xffffffffu, s, o);
    if ((tid & 31) == 0) red[tid >> 5] = s;
    __syncthreads();
    float tot = 0.f;
    #pragma unroll
    for (int i = 0; i < 8; i++) tot += red[i];
    float inv = rsqrtf(tot / (float)cols + 1e-6f);
    for (int c = tid; c < cols; c += 256)
        out[(size_t)row * cols + c] = __float2half_rn(xr[c] * inv * w[c]);
}

// ---------------- ldmatrix helpers ----------------
__device__ __forceinline__ void ldsm4(uint32_t& r0, uint32_t& r1, uint32_t& r2, uint32_t& r3,
                                      uint32_t addr) {
    asm volatile("ldmatrix.sync.aligned.m8n8.x4.shared.b16 {%0,%1,%2,%3}, [%4];"
                 : "=r"(r0), "=r"(r1), "=r"(r2), "=r"(r3) : "r"(addr));
}
__device__ __forceinline__ void ldsm4t(uint32_t& r0, uint32_t& r1, uint32_t& r2, uint32_t& r3,
                                       uint32_t addr) {
    asm volatile("ldmatrix.sync.aligned.m8n8.x4.trans.shared.b16 {%0,%1,%2,%3}, [%4];"
                 : "=r"(r0), "=r"(r1), "=r"(r2), "=r"(r3) : "r"(addr));
}
#define MMA16816(acc, a0, a1, a2, a3, b0, b1)                                   \
    asm volatile("mma.sync.aligned.m16n8k16.row.col.f32.f16.f16.f32 "           \
                 "{%0,%1,%2,%3}, {%4,%5,%6,%7}, {%8,%9}, {%0,%1,%2,%3};"        \
                 : "+f"((acc)[0]), "+f"((acc)[1]), "+f"((acc)[2]), "+f"((acc)[3]) \
                 : "r"(a0), "r"(a1), "r"(a2), "r"(a3), "r"(b0), "r"(b1))

__device__ __forceinline__ float silu_f(float x) {
    return x / (1.0f + __expf(-x));
}

// ---------------- FP16 mma.sync GEMM (fp32 acc), BK=64, 3-stage, ldmatrix -
// 128 threads = 4 warps (2m x 2n), warp tile 64x64, CTA tile 128x128.
// BK=64 halves barrier/wait overhead per FLOP vs BK=32.
// EPI: 0 = fp32 C              1 = fp32 C, C = acc + R(fp32)
//      2 = fp16 C              3 = fp16 C, C = silu(R(fp16)) * acc
#define HPITCH 72                          // 64 data halves + 8 pad (bank phase 4i)
#define HSTG  (128*HPITCH)                 // halves per matrix per stage
#define GEMM_SMEM (3*2*HSTG*2)             // 110592 B: 3 stages x (A + W)
template<int EPI>
__global__ void __launch_bounds__(128, 2)
h16gemm(const __half* __restrict__ A, const __half* __restrict__ W,
        const void* __restrict__ Rv, void* __restrict__ Cv,
        int M, int N, int K) {
    extern __shared__ __half smh[];
    const uint32_t sbase = (uint32_t)__cvta_generic_to_shared(smh);

    const int tid  = threadIdx.x;
    const int warp = tid >> 5, lane = tid & 31;
    const int wm = warp >> 1;              // 0..1 -> 64 rows
    const int wn = warp & 1;               // 0..1 -> 64 cols
    const int g = lane >> 2, t = lane & 3;
    const int bm = blockIdx.y * 128;
    const int bn = blockIdx.x * 128;

    float acc[4][8][4];
    #pragma unroll
    for (int i = 0; i < 4; i++)
        #pragma unroll
        for (int j = 0; j < 8; j++)
            #pragma unroll
            for (int c = 0; c < 4; c++) acc[i][j][c] = 0.f;

    const int arow = wm * 64 + (lane & 15);
    const int acol = (lane >> 4) << 3;
    const int brow = wn * 64 + ((lane >> 4) << 3) + (lane & 7);
    const int bcol = ((lane >> 3) & 1) << 3;

    auto load_stage = [&](int s, int k0) {
        uint32_t sA = sbase + (uint32_t)(s * 2 * HSTG) * 2;
        uint32_t sW = sA + (uint32_t)HSTG * 2;
        #pragma unroll
        for (int i = 0; i < 8; i++) {
            int ch = tid + 128 * i;        // 0..1023
            int m = ch >> 3, c8 = (ch & 7) * 8;
            uint32_t d = sA + (uint32_t)(m * HPITCH + c8) * 2;
            const __half* src = &A[(size_t)(bm + m) * K + k0 + c8];
            asm volatile("cp.async.cg.shared.global [%0], [%1], 16;" :: "r"(d), "l"(src));
            int n = bn + m;
            int ok = (n < N) ? 16 : 0;
            uint32_t dw = sW + (uint32_t)(m * HPITCH + c8) * 2;
            const __half* srcw = &W[(size_t)(n < N ? n : 0) * K + k0 + c8];
            asm volatile("cp.async.cg.shared.global [%0], [%1], 16, %2;"
                         :: "r"(dw), "l"(srcw), "r"(ok));
        }
        asm volatile("cp.async.commit_group;" ::: "memory");
    };

    auto compute = [&](int s) {
        uint32_t sA = sbase + (uint32_t)(s * 2 * HSTG) * 2;
        uint32_t sW = sA + (uint32_t)HSTG * 2;
        #pragma unroll
        for (int ks = 0; ks < 4; ks++) {
            int kk = ks * 16;
            uint32_t af[4][4];
            #pragma unroll
            for (int i = 0; i < 4; i++)
                ldsm4(af[i][0], af[i][1], af[i][2], af[i][3],
                      sA + (uint32_t)((arow + i * 16) * HPITCH + kk + acol) * 2);
            uint32_t bf[8][2];
            #pragma unroll
            for (int jj = 0; jj < 4; jj++)
                ldsm4(bf[2 * jj][0], bf[2 * jj][1], bf[2 * jj + 1][0], bf[2 * jj + 1][1],
                      sW + (uint32_t)((jj * 16 + brow) * HPITCH + kk + bcol) * 2);
            #pragma unroll
            for (int i = 0; i < 4; i++)
                #pragma unroll
                for (int j = 0; j < 8; j++)
                    MMA16816(acc[i][j], af[i][0], af[i][1], af[i][2], af[i][3],
                             bf[j][0], bf[j][1]);
        }
    };

    const int NK = K >> 6;                 // BK = 64
    load_stage(0, 0);
    load_stage(1, 64);

    for (int i = 0; i < NK; i++) {
        if (i + 1 < NK) asm volatile("cp.async.wait_group 1;" ::: "memory");
        else            asm volatile("cp.async.wait_group 0;" ::: "memory");
        __syncthreads();
        if (i + 2 < NK) load_stage((i + 2) % 3, (i + 2) * 64);
        compute(i % 3);
    }

    // ---- epilogue ----
    #pragma unroll
    for (int i = 0; i < 4; i++) {
        int r0 = bm + wm * 64 + i * 16 + g;
        #pragma unroll
        for (int j = 0; j < 8; j++) {
            int c = bn + wn * 64 + j * 8 + 2 * t;
            if (c < N) {
                #pragma unroll
                for (int half = 0; half < 2; half++) {
                    int rr = r0 + half * 8;
                    float a0 = acc[i][j][2 * half], a1 = acc[i][j][2 * half + 1];
                    size_t idx = (size_t)rr * N + c;
                    if (EPI == 0) {
                        *(float2*)&((float*)Cv)[idx] = make_float2(a0, a1);
                    } else if (EPI == 1) {
                        float2 r = *(const float2*)&((const float*)Rv)[idx];
                        *(float2*)&((float*)Cv)[idx] = make_float2(a0 + r.x, a1 + r.y);
                    } else if (EPI == 2) {
                        *(__half2*)&((__half*)Cv)[idx] = __floats2half2_rn(a0, a1);
                    } else {
                        __half2 gh2 = *(const __half2*)&((const __half*)Rv)[idx];
                        float g0 = __half2float(gh2.x), g1 = __half2float(gh2.y);
                        *(__half2*)&((__half*)Cv)[idx] =
                            __floats2half2_rn(silu_f(g0) * a0, silu_f(g1) * a1);
                    }
                }
            }
        }
    }
}

// ---------------- RoPE (yarn) helpers ----------------
__device__ __forceinline__ void yarn_cossin(int j, int pos, float& c, float& s) {
    float ar = (float)j * (1.0f / 32.0f);
    float fe = __powf(10000.0f, -ar);
    float fi = fe * (1.0f / 40.0f);
    float ramp = fminf(fmaxf(((float)j - 10.0f) * (1.0f / 13.0f), 0.0f), 1.0f);
    float f = fi * ramp + fe * (1.0f - ramp);
    float a = (float)pos * f;
    c = cosf(a); s = sinf(a);
}

// q fp16 [NTOK, NH*DQ] -> qf fp16 [B,H,S,DQ] with rope on last 64
__global__ void build_qf(const __half* __restrict__ q, const int* __restrict__ pos_ids,
                         __half* __restrict__ qf) {
    int t = blockIdx.x;
    int b = t / SEQ, s = t % SEQ;
    int tid = threadIdx.x;              // 128
    __shared__ float cs[32], sn[32];
    int pos = pos_ids[t];
    if (tid < 32) yarn_cossin(tid, pos, cs[tid], sn[tid]);
    __syncthreads();
    for (int h = 0; h < NH; h++) {
        size_t src = (size_t)t * (NH * DQ) + h * DQ;
        size_t dst = ((size_t)(b * NH + h) * SEQ + s) * DQ;
        qf[dst + tid] = q[src + tid];
        if (tid < 32) {
            float p0 = __half2float(q[src + DNOPE + 2 * tid]);
            float p1 = __half2float(q[src + DNOPE + 2 * tid + 1]);
            qf[dst + DNOPE + tid]      = __float2half_rn(p0 * cs[tid] - p1 * sn[tid]);
            qf[dst + DNOPE + 32 + tid] = __float2half_rn(p1 * cs[tid] + p0 * sn[tid]);
        }
    }
}

// kv fp16 [NTOK, NH*256], ckv fp32 -> kf fp16 [B,H,S,192], v fp16 [B,H,S,128]
__global__ void build_kf(const __half* __restrict__ kv, const float* __restrict__ ckv,
                         const int* __restrict__ pos_ids,
                         __half* __restrict__ kf, __half* __restrict__ vv) {
    int t = blockIdx.x;
    int b = t / SEQ, s = t % SEQ;
    int tid = threadIdx.x;              // 128
    __shared__ float cs[32], sn[32], kr[64];
    int pos = pos_ids[t];
    if (tid < 32) yarn_cossin(tid, pos, cs[tid], sn[tid]);
    __syncthreads();
    if (tid < 32) {
        float p0 = ckv[(size_t)t * (KVR + DROPE) + KVR + 2 * tid];
        float p1 = ckv[(size_t)t * (KVR + DROPE) + KVR + 2 * tid + 1];
        kr[tid]      = p0 * cs[tid] - p1 * sn[tid];
        kr[tid + 32] = p1 * cs[tid] + p0 * sn[tid];
    }
    __syncthreads();
    for (int h = 0; h < NH; h++) {
        size_t src = (size_t)t * (NH * 256) + h * 256;
        size_t d0 = ((size_t)(b * NH + h) * SEQ + s);
        kf[d0 * DQ + tid] = kv[src + tid];
        vv[d0 * DV + tid] = kv[src + DNOPE + tid];
        if (tid < 64) kf[d0 * DQ + DNOPE + tid] = __float2half_rn(kr[tid]);
    }
}

// ---------------- Tensor-core flash attention (single K/V buffer, 3 CTA/SM)
#define QPITCH 200
#define VPITCH 136
#define ATT_SMEM ((2*64*QPITCH + 64*VPITCH) * 2)
__global__ void __launch_bounds__(128)
attn_tc(const __half* __restrict__ qf, const __half* __restrict__ kf,
        const __half* __restrict__ vv, __half* __restrict__ out) {
    extern __shared__ __half sm[];
    const uint32_t sQ = (uint32_t)__cvta_generic_to_shared(sm);
    const uint32_t sK = sQ + 64 * QPITCH * 2;
    const uint32_t sV = sK + 64 * QPITCH * 2;
    const int tid = threadIdx.x, warp = tid >> 5, lane = tid & 31;
    const int g = lane >> 2, t = lane & 3;
    const int b = blockIdx.z, h = blockIdx.y;
    const int q0 = ((int)gridDim.x - 1 - (int)blockIdx.x) * 64;
    const __half* Qg = qf + (size_t)(b * NH + h) * SEQ * DQ;
    const __half* Kg = kf + (size_t)(b * NH + h) * SEQ * DQ;
    const __half* Vg = vv + (size_t)(b * NH + h) * SEQ * DV;
    const int wrow = warp * 16;
    const float scale = 0.07216878364870323f;    // 192^-0.5

    #pragma unroll
    for (int i = 0; i < 12; i++) {
        int ch = tid + 128 * i;
        int r = ch / 24, c = (ch % 24) * 8;
        uint32_t d = sQ + (uint32_t)(r * QPITCH + c) * 2;
        const __half* src = Qg + (size_t)(q0 + r) * DQ + c;
        asm volatile("cp.async.cg.shared.global [%0], [%1], 16;" :: "r"(d), "l"(src));
    }
    asm volatile("cp.async.commit_group;" ::: "memory");

    float o[16][4];
    #pragma unroll
    for (int i = 0; i < 16; i++)
        #pragma unroll
        for (int c = 0; c < 4; c++) o[i][c] = 0.f;
    float m0 = -INFINITY, m1 = -INFINITY, l0 = 0.f, l1 = 0.f;

    const uint32_t aoff = (uint32_t)((wrow + (lane & 15)) * QPITCH + ((lane >> 4) << 3)) * 2;
    const int brow = ((lane >> 4) << 3) + (lane & 7);
    const int bcol = ((lane >> 3) & 1) << 3;
    const int vrow = lane & 15;
    const int vcol = ((lane >> 4) << 3);

    for (int kc = 0; kc <= q0; kc += 64) {
        __syncthreads();
        #pragma unroll
        for (int i = 0; i < 12; i++) {
            int ch = tid + 128 * i;
            int r = ch / 24, c = (ch % 24) * 8;
            uint32_t d = sK + (uint32_t)(r * QPITCH + c) * 2;
            const __half* src = Kg + (size_t)(kc + r) * DQ + c;
            asm volatile("cp.async.cg.shared.global [%0], [%1], 16;" :: "r"(d), "l"(src));
        }
        #pragma unroll
        for (int i = 0; i < 8; i++) {
            int ch = tid + 128 * i;
            int r = ch / 16, c = (ch % 16) * 8;
            uint32_t d = sV + (uint32_t)(r * VPITCH + c) * 2;
            const __half* src = Vg + (size_t)(kc + r) * DV + c;
            asm volatile("cp.async.cg.shared.global [%0], [%1], 16;" :: "r"(d), "l"(src));
        }
        asm volatile("cp.async.commit_group;" ::: "memory");
        asm volatile("cp.async.wait_group 0;" ::: "memory");
        __syncthreads();

        // ---- S = Q @ K^T ----
        float sacc[8][4];
        #pragma unroll
        for (int nt = 0; nt < 8; nt++)
            #pragma unroll
            for (int c = 0; c < 4; c++) sacc[nt][c] = 0.f;
        #pragma unroll
        for (int kt = 0; kt < 12; kt++) {
            uint32_t a0, a1, a2, a3;
            ldsm4(a0, a1, a2, a3, sQ + aoff + kt * 32);
            uint32_t bf[8][2];
            #pragma unroll
            for (int jj = 0; jj < 4; jj++)
                ldsm4(bf[2 * jj][0], bf[2 * jj][1], bf[2 * jj + 1][0], bf[2 * jj + 1][1],
                      sK + (uint32_t)((jj * 16 + brow) * QPITCH + kt * 16 + bcol) * 2);
            #pragma unroll
            for (int nt = 0; nt < 8; nt++)
                MMA16816(sacc[nt], a0, a1, a2, a3, bf[nt][0], bf[nt][1]);
        }
        int r0w = q0 + wrow + g, r1w = r0w + 8;
        #pragma unroll
        for (int nt = 0; nt < 8; nt++)
            #pragma unroll
            for (int c = 0; c < 4; c++) sacc[nt][c] *= scale;
        if (kc == q0) {
            #pragma unroll
            for (int nt = 0; nt < 8; nt++) {
                int c0 = kc + nt * 8 + 2 * t;
                if (c0     > r0w) sacc[nt][0] = -INFINITY;
                if (c0 + 1 > r0w) sacc[nt][1] = -INFINITY;
                if (c0     > r1w) sacc[nt][2] = -INFINITY;
                if (c0 + 1 > r1w) sacc[nt][3] = -INFINITY;
            }
        }
        // ---- online softmax ----
        float mx0 = -INFINITY, mx1 = -INFINITY;
        #pragma unroll
        for (int nt = 0; nt < 8; nt++) {
            mx0 = fmaxf(mx0, fmaxf(sacc[nt][0], sacc[nt][1]));
            mx1 = fmaxf(mx1, fmaxf(sacc[nt][2], sacc[nt][3]));
        }
        mx0 = fmaxf(mx0, __shfl_xor_sync(0xffffffffu, mx0, 1));
        mx0 = fmaxf(mx0, __shfl_xor_sync(0xffffffffu, mx0, 2));
        mx1 = fmaxf(mx1, __shfl_xor_sync(0xffffffffu, mx1, 1));
        mx1 = fmaxf(mx1, __shfl_xor_sync(0xffffffffu, mx1, 2));
        float nm0 = fmaxf(m0, mx0), nm1 = fmaxf(m1, mx1);
        float cf0 = __expf(m0 - nm0), cf1 = __expf(m1 - nm1);
        float s0 = 0.f, s1 = 0.f;
        uint32_t ph01[8], ph23[8];
        #pragma unroll
        for (int nt = 0; nt < 8; nt++) {
            float p0 = __expf(sacc[nt][0] - nm0);
            float p1 = __expf(sacc[nt][1] - nm0);
            float p2 = __expf(sacc[nt][2] - nm1);
            float p3 = __expf(sacc[nt][3] - nm1);
            s0 += p0 + p1; s1 += p2 + p3;
            __half2 q01 = __floats2half2_rn(p0, p1);
            __half2 q23 = __floats2half2_rn(p2, p3);
            ph01[nt] = *(uint32_t*)&q01;
            ph23[nt] = *(uint32_t*)&q23;
        }
        s0 += __shfl_xor_sync(0xffffffffu, s0, 1);
        s0 += __shfl_xor_sync(0xffffffffu, s0, 2);
        s1 += __shfl_xor_sync(0xffffffffu, s1, 1);
        s1 += __shfl_xor_sync(0xffffffffu, s1, 2);
        l0 = l0 * cf0 + s0;
        l1 = l1 * cf1 + s1;
        m0 = nm0; m1 = nm1;
        #pragma unroll
        for (int nv = 0; nv < 16; nv++) {
            o[nv][0] *= cf0; o[nv][1] *= cf0;
            o[nv][2] *= cf1; o[nv][3] *= cf1;
        }
        // ---- O += P @ V ----
        #pragma unroll
        for (int kt2 = 0; kt2 < 4; kt2++) {
            uint32_t a0 = ph01[2 * kt2], a1 = ph23[2 * kt2];
            uint32_t a2 = ph01[2 * kt2 + 1], a3 = ph23[2 * kt2 + 1];
            #pragma unroll
            for (int jv = 0; jv < 8; jv++) {
                uint32_t b0, b1, b2, b3;
                ldsm4t(b0, b1, b2, b3,
                       sV + (uint32_t)((kt2 * 16 + vrow) * VPITCH + jv * 16 + vcol) * 2);
                MMA16816(o[2 * jv],     a0, a1, a2, a3, b0, b1);
                MMA16816(o[2 * jv + 1], a0, a1, a2, a3, b2, b3);
            }
        }
    }

    float inv0 = 1.f / l0, inv1 = 1.f / l1;
    int r0w = q0 + wrow + g, r1w = r0w + 8;
    #pragma unroll
    for (int nv = 0; nv < 16; nv++) {
        int col = nv * 8 + 2 * t;
        __half2 v0 = __floats2half2_rn(o[nv][0] * inv0, o[nv][1] * inv0);
        __half2 v1 = __floats2half2_rn(o[nv][2] * inv1, o[nv][3] * inv1);
        *(__half2*)&out[(size_t)(b * SEQ + r0w) * (NH * DV) + h * DV + col] = v0;
        *(__half2*)&out[(size_t)(b * SEQ + r1w) * (NH * DV) + h * DV + col] = v1;
    }
}

// ---------------- Launch ----------------
extern "C" void kernel_launch(void* const* d_in, const int* in_sizes, int n_in,
                              void* d_out, int out_size) {
    const float* hidden = (const float*)d_in[0];
    const int*   pos    = (const int*)d_in[1];
    const float* Wq     = (const float*)d_in[2];
    const float* Wkva   = (const float*)d_in[3];
    const float* w_kvln = (const float*)d_in[4];
    const float* Wkvb   = (const float*)d_in[5];
    const float* Wo     = (const float*)d_in[6];
    const float* Wg     = (const float*)d_in[7];
    const float* Wu     = (const float*)d_in[8];
    const float* Wd     = (const float*)d_in[9];
    const float* w_ln1  = (const float*)d_in[10];
    const float* w_ln2  = (const float*)d_in[11];
    float* out = (float*)d_out;

    __half *xln, *cln, *attn, *yh, *ggh, *gh, *qh, *kvh, *qfp, *kfp, *vp;
    __half *wq, *wkva, *wkvb, *wo, *wg, *wu, *wd;
    float *ckv, *x1;
    cudaGetSymbolAddress((void**)&xln,  h_xln);
    cudaGetSymbolAddress((void**)&cln,  h_cln);
    cudaGetSymbolAddress((void**)&attn, h_attn);
    cudaGetSymbolAddress((void**)&yh,   h_y);
    cudaGetSymbolAddress((void**)&ggh,  h_gg);
    cudaGetSymbolAddress((void**)&gh,   h_gh);
    cudaGetSymbolAddress((void**)&qh,   h_q);
    cudaGetSymbolAddress((void**)&kvh,  h_kv);
    cudaGetSymbolAddress((void**)&qfp,  h_qf);
    cudaGetSymbolAddress((void**)&kfp,  h_kf);
    cudaGetSymbolAddress((void**)&vp,   h_v);
    cudaGetSymbolAddress((void**)&wq,   hw_q);
    cudaGetSymbolAddress((void**)&wkva, hw_kva);
    cudaGetSymbolAddress((void**)&wkvb, hw_kvb);
    cudaGetSymbolAddress((void**)&wo,   hw_o);
    cudaGetSymbolAddress((void**)&wg,   hw_g);
    cudaGetSymbolAddress((void**)&wu,   hw_u);
    cudaGetSymbolAddress((void**)&wd,   hw_d);
    cudaGetSymbolAddress((void**)&ckv,  g_ckv);
    cudaGetSymbolAddress((void**)&x1,   g_x1);

    cudaFuncSetAttribute(h16gemm<0>, cudaFuncAttributeMaxDynamicSharedMemorySize, GEMM_SMEM);
    cudaFuncSetAttribute(h16gemm<1>, cudaFuncAttributeMaxDynamicSharedMemorySize, GEMM_SMEM);
    cudaFuncSetAttribute(h16gemm<2>, cudaFuncAttributeMaxDynamicSharedMemorySize, GEMM_SMEM);
    cudaFuncSetAttribute(h16gemm<3>, cudaFuncAttributeMaxDynamicSharedMemorySize, GEMM_SMEM);
    cudaFuncSetAttribute(attn_tc, cudaFuncAttributeMaxDynamicSharedMemorySize, ATT_SMEM);

    dim3 blk(256);
    auto cvt = [&](const float* s, __half* d, int n) {
        int n4 = n / 4;
        w2h_kernel<<<(n4 + 255) / 256, 256>>>(s, d, n4);
    };
    // launch order: #4 = Wq GEMM (profiled slot)
    cvt(Wq, wq, NH * DQ * HID);                                     // 1
    rmsnorm_kernel<<<NTOK, blk>>>(hidden, w_ln1, xln, HID, HID);    // 2
    cvt(Wkva, wkva, (KVR + DROPE) * HID);                           // 3
    // 4: q = xln @ Wq^T (fp16 out)  [4096 x 3072] K=2048
    h16gemm<2><<<dim3(24, 32), 128, GEMM_SMEM>>>(xln, wq, nullptr, qh, NTOK, NH * DQ, HID);
    // ckv = xln @ Wkva^T (fp32 out)
    h16gemm<0><<<dim3(5, 32), 128, GEMM_SMEM>>>(xln, wkva, nullptr, ckv, NTOK, KVR + DROPE, HID);
    rmsnorm_kernel<<<NTOK, blk>>>(ckv, w_kvln, cln, KVR, KVR + DROPE);
    cvt(Wkvb, wkvb, NH * (DNOPE + DV) * KVR);
    // kv = c_ln @ Wkvb^T (fp16 out)  K=512
    h16gemm<2><<<dim3(32, 32), 128, GEMM_SMEM>>>(cln, wkvb, nullptr, kvh, NTOK, NH * 256, KVR);
    build_qf<<<NTOK, 128>>>(qh, pos, qfp);
    build_kf<<<NTOK, 128>>>(kvh, ckv, pos, kfp, vp);
    // tensor-core flash attention
    attn_tc<<<dim3(SEQ / 64, NH, BATCH), 128, ATT_SMEM>>>(qfp, kfp, vp, attn);
    cvt(Wo, wo, HID * NH * DV);
    // x1 = hidden + attn @ Wo^T
    h16gemm<1><<<dim3(16, 32), 128, GEMM_SMEM>>>(attn, wo, hidden, x1, NTOK, HID, NH * DV);
    rmsnorm_kernel<<<NTOK, blk>>>(x1, w_ln2, yh, HID, HID);
    cvt(Wg, wg, INTER * HID);
    cvt(Wu, wu, INTER * HID);
    cvt(Wd, wd, HID * INTER);
    // g = y @ Wg^T (fp16 out)
    h16gemm<2><<<dim3(86, 32), 128, GEMM_SMEM>>>(yh, wg, nullptr, ggh, NTOK, INTER, HID);
    // gh = silu(g) * (y @ Wu^T)  (fused epilogue, fp16 out)
    h16gemm<3><<<dim3(86, 32), 128, GEMM_SMEM>>>(yh, wu, ggh, gh, NTOK, INTER, HID);
    // out = x1 + gh @ Wd^T  K=10944
    h16gemm<1><<<dim3(16, 32), 128, GEMM_SMEM>>>(gh, wd, x1, out, NTOK, HID, INTER);
}

// round 16
// speedup vs baseline: 1.1319x; 1.0209x over previous
#include <cuda_runtime.h>
#include <cuda_fp16.h>
#include <math.h>
#include <stdint.h>

// ---------------- Problem constants (fixed shapes) ----------------
#define BATCH 2
#define SEQ   2048
#define NTOK  (BATCH*SEQ)        // 4096
#define HID   2048
#define NH    16
#define DQ    192
#define DNOPE 128
#define DROPE 64
#define DV    128
#define KVR   512
#define INTER 10944

// ---------------- Scratch (device globals; allocation-free) ----------------
__device__ __half h_xln [NTOK*HID];
__device__ __half h_cln [NTOK*KVR];
__device__ __half h_attn[NTOK*HID];
__device__ __half h_y   [NTOK*HID];
__device__ __half h_gg  [NTOK*INTER];
__device__ __half h_gh  [NTOK*INTER];
__device__ __half h_q   [NTOK*NH*DQ];
__device__ __half h_kv  [NTOK*NH*(DNOPE+DV)];
__device__ __half h_qf  [BATCH*NH*SEQ*DQ];
__device__ __half h_kf  [BATCH*NH*SEQ*DQ];
__device__ __half h_v   [BATCH*NH*SEQ*DV];
__device__ float g_ckv [NTOK*(KVR+DROPE)];
__device__ float g_x1  [NTOK*HID];
// fp16 weight copies
__device__ __half hw_q  [NH*DQ*HID];
__device__ __half hw_kva[(KVR+DROPE)*HID];
__device__ __half hw_kvb[NH*(DNOPE+DV)*KVR];
__device__ __half hw_o  [HID*NH*DV];
__device__ __half hw_g  [INTER*HID];
__device__ __half hw_u  [INTER*HID];
__device__ __half hw_d  [HID*INTER];

// ---------------- weight fp32 -> fp16 (MLP=4: 4 independent float4/thread) -
__global__ void w2h_kernel(const float* __restrict__ in, __half* __restrict__ out, int n4) {
    int base = blockIdx.x * blockDim.x * 4 + threadIdx.x;
    float4 v[4];
    int idx[4];
    #pragma unroll
    for (int j = 0; j < 4; j++) {
        idx[j] = base + j * blockDim.x;
        if (idx[j] < n4) v[j] = ((const float4*)in)[idx[j]];
    }
    #pragma unroll
    for (int j = 0; j < 4; j++) {
        if (idx[j] < n4) {
            __half2 h0 = __floats2half2_rn(v[j].x, v[j].y);
            __half2 h1 = __floats2half2_rn(v[j].z, v[j].w);
            ((uint2*)out)[idx[j]] = make_uint2(*(uint32_t*)&h0, *(uint32_t*)&h1);
        }
    }
}

// ---------------- RMSNorm (fp32 in, fp16 out) ----------------
__global__ void rmsnorm_kernel(const float* __restrict__ in, const float* __restrict__ w,
                               __half* __restrict__ out, int cols, int instride) {
    int row = blockIdx.x;
    int tid = threadIdx.x;
    const float* xr = in + (size_t)row * instride;
    float s = 0.f;
    for (int c = tid; c < cols; c += 256) { float v = xr[c]; s += v * v; }
    __shared__ float red[8];
    for (int o = 16; o; o >>= 1) s += __shfl_xor_sync(0xffffffffu, s, o);
    if ((tid & 31) == 0) red[tid >> 5] = s;
    __syncthreads();
    float tot = 0.f;
    #pragma unroll
    for (int i = 0; i < 8; i++) tot += red[i];
    float inv = rsqrtf(tot / (float)cols + 1e-6f);
    for (int c = tid; c < cols; c += 256)
        out[(size_t)row * cols + c] = __float2half_rn(xr[c] * inv * w[c]);
}

// ---------------- ldmatrix helpers ----------------
__device__ __forceinline__ void ldsm4(uint32_t& r0, uint32_t& r1, uint32_t& r2, uint32_t& r3,
                                      uint32_t addr) {
    asm volatile("ldmatrix.sync.aligned.m8n8.x4.shared.b16 {%0,%1,%2,%3}, [%4];"
                 : "=r"(r0), "=r"(r1), "=r"(r2), "=r"(r3) : "r"(addr));
}
__device__ __forceinline__ void ldsm4t(uint32_t& r0, uint32_t& r1, uint32_t& r2, uint32_t& r3,
                                       uint32_t addr) {
    asm volatile("ldmatrix.sync.aligned.m8n8.x4.trans.shared.b16 {%0,%1,%2,%3}, [%4];"
                 : "=r"(r0), "=r"(r1), "=r"(r2), "=r"(r3) : "r"(addr));
}
#define MMA16816(acc, a0, a1, a2, a3, b0, b1)                                   \
    asm volatile("mma.sync.aligned.m16n8k16.row.col.f32.f16.f16.f32 "           \
                 "{%0,%1,%2,%3}, {%4,%5,%6,%7}, {%8,%9}, {%0,%1,%2,%3};"        \
                 : "+f"((acc)[0]), "+f"((acc)[1]), "+f"((acc)[2]), "+f"((acc)[3]) \
                 : "r"(a0), "r"(a1), "r"(a2), "r"(a3), "r"(b0), "r"(b1))

__device__ __forceinline__ float silu_f(float x) {
    return x / (1.0f + __expf(-x));
}

// ---------------- FP16 mma.sync GEMM (fp32 acc), 3-stage, ldmatrix --------
// R11 config: 128 threads = 4 warps (2m x 2n), warp tile 64x64, BK=32.
// EPI: 0 = fp32 C              1 = fp32 C, C = acc + R(fp32)
//      2 = fp16 C              3 = fp16 C, C = silu(R(fp16)) * acc
#define HPITCH 40
#define HSTG  (128*HPITCH)
#define GEMM_SMEM (3*2*HSTG*2)
template<int EPI>
__global__ void __launch_bounds__(128, 2)
h16gemm(const __half* __restrict__ A, const __half* __restrict__ W,
        const void* __restrict__ Rv, void* __restrict__ Cv,
        int M, int N, int K) {
    extern __shared__ __half smh[];
    const uint32_t sbase = (uint32_t)__cvta_generic_to_shared(smh);

    const int tid  = threadIdx.x;
    const int warp = tid >> 5, lane = tid & 31;
    const int wm = warp >> 1;
    const int wn = warp & 1;
    const int g = lane >> 2, t = lane & 3;
    const int bm = blockIdx.y * 128;
    const int bn = blockIdx.x * 128;

    float acc[4][8][4];
    #pragma unroll
    for (int i = 0; i < 4; i++)
        #pragma unroll
        for (int j = 0; j < 8; j++)
            #pragma unroll
            for (int c = 0; c < 4; c++) acc[i][j][c] = 0.f;

    const int arow = wm * 64 + (lane & 15);
    const int acol = (lane >> 4) << 3;
    const int brow = wn * 64 + ((lane >> 4) << 3) + (lane & 7);
    const int bcol = ((lane >> 3) & 1) << 3;

    auto load_stage = [&](int s, int k0) {
        uint32_t sA = sbase + (uint32_t)(s * 2 * HSTG) * 2;
        uint32_t sW = sA + (uint32_t)HSTG * 2;
        #pragma unroll
        for (int i = 0; i < 4; i++) {
            int ch = tid + 128 * i;
            int m = ch >> 2, c8 = (ch & 3) * 8;
            uint32_t d = sA + (uint32_t)(m * HPITCH + c8) * 2;
            const __half* src = &A[(size_t)(bm + m) * K + k0 + c8];
            asm volatile("cp.async.cg.shared.global [%0], [%1], 16;" :: "r"(d), "l"(src));
            int n = bn + m;
            int ok = (n < N) ? 16 : 0;
            uint32_t dw = sW + (uint32_t)(m * HPITCH + c8) * 2;
            const __half* srcw = &W[(size_t)(n < N ? n : 0) * K + k0 + c8];
            asm volatile("cp.async.cg.shared.global [%0], [%1], 16, %2;"
                         :: "r"(dw), "l"(srcw), "r"(ok));
        }
        asm volatile("cp.async.commit_group;" ::: "memory");
    };

    auto compute = [&](int s) {
        uint32_t sA = sbase + (uint32_t)(s * 2 * HSTG) * 2;
        uint32_t sW = sA + (uint32_t)HSTG * 2;
        #pragma unroll
        for (int ks = 0; ks < 2; ks++) {
            int kk = ks * 16;
            uint32_t af[4][4];
            #pragma unroll
            for (int i = 0; i < 4; i++)
                ldsm4(af[i][0], af[i][1], af[i][2], af[i][3],
                      sA + (uint32_t)((arow + i * 16) * HPITCH + kk + acol) * 2);
            uint32_t bf[8][2];
            #pragma unroll
            for (int jj = 0; jj < 4; jj++)
                ldsm4(bf[2 * jj][0], bf[2 * jj][1], bf[2 * jj + 1][0], bf[2 * jj + 1][1],
                      sW + (uint32_t)((jj * 16 + brow) * HPITCH + kk + bcol) * 2);
            #pragma unroll
            for (int i = 0; i < 4; i++)
                #pragma unroll
                for (int j = 0; j < 8; j++)
                    MMA16816(acc[i][j], af[i][0], af[i][1], af[i][2], af[i][3],
                             bf[j][0], bf[j][1]);
        }
    };

    const int NK = K >> 5;
    load_stage(0, 0);
    load_stage(1, 32);

    for (int i = 0; i < NK; i++) {
        if (i + 1 < NK) asm volatile("cp.async.wait_group 1;" ::: "memory");
        else            asm volatile("cp.async.wait_group 0;" ::: "memory");
        __syncthreads();
        if (i + 2 < NK) load_stage((i + 2) % 3, (i + 2) * 32);
        compute(i % 3);
    }

    // ---- epilogue ----
    #pragma unroll
    for (int i = 0; i < 4; i++) {
        int r0 = bm + wm * 64 + i * 16 + g;
        #pragma unroll
        for (int j = 0; j < 8; j++) {
            int c = bn + wn * 64 + j * 8 + 2 * t;
            if (c < N) {
                #pragma unroll
                for (int half = 0; half < 2; half++) {
                    int rr = r0 + half * 8;
                    float a0 = acc[i][j][2 * half], a1 = acc[i][j][2 * half + 1];
                    size_t idx = (size_t)rr * N + c;
                    if (EPI == 0) {
                        *(float2*)&((float*)Cv)[idx] = make_float2(a0, a1);
                    } else if (EPI == 1) {
                        float2 r = *(const float2*)&((const float*)Rv)[idx];
                        *(float2*)&((float*)Cv)[idx] = make_float2(a0 + r.x, a1 + r.y);
                    } else if (EPI == 2) {
                        *(__half2*)&((__half*)Cv)[idx] = __floats2half2_rn(a0, a1);
                    } else {
                        __half2 gh2 = *(const __half2*)&((const __half*)Rv)[idx];
                        float g0 = __half2float(gh2.x), g1 = __half2float(gh2.y);
                        *(__half2*)&((__half*)Cv)[idx] =
                            __floats2half2_rn(silu_f(g0) * a0, silu_f(g1) * a1);
                    }
                }
            }
        }
    }
}

// ---------------- RoPE (yarn) helpers ----------------
__device__ __forceinline__ void yarn_cossin(int j, int pos, float& c, float& s) {
    float ar = (float)j * (1.0f / 32.0f);
    float fe = __powf(10000.0f, -ar);
    float fi = fe * (1.0f / 40.0f);
    float ramp = fminf(fmaxf(((float)j - 10.0f) * (1.0f / 13.0f), 0.0f), 1.0f);
    float f = fi * ramp + fe * (1.0f - ramp);
    float a = (float)pos * f;
    c = cosf(a); s = sinf(a);
}

// q fp16 [NTOK, NH*DQ] -> qf fp16 [B,H,S,DQ] with rope on last 64
__global__ void build_qf(const __half* __restrict__ q, const int* __restrict__ pos_ids,
                         __half* __restrict__ qf) {
    int t = blockIdx.x;
    int b = t / SEQ, s = t % SEQ;
    int tid = threadIdx.x;              // 128
    __shared__ float cs[32], sn[32];
    int pos = pos_ids[t];
    if (tid < 32) yarn_cossin(tid, pos, cs[tid], sn[tid]);
    __syncthreads();
    for (int h = 0; h < NH; h++) {
        size_t src = (size_t)t * (NH * DQ) + h * DQ;
        size_t dst = ((size_t)(b * NH + h) * SEQ + s) * DQ;
        qf[dst + tid] = q[src + tid];
        if (tid < 32) {
            float p0 = __half2float(q[src + DNOPE + 2 * tid]);
            float p1 = __half2float(q[src + DNOPE + 2 * tid + 1]);
            qf[dst + DNOPE + tid]      = __float2half_rn(p0 * cs[tid] - p1 * sn[tid]);
            qf[dst + DNOPE + 32 + tid] = __float2half_rn(p1 * cs[tid] + p0 * sn[tid]);
        }
    }
}

// kv fp16 [NTOK, NH*256], ckv fp32 -> kf fp16 [B,H,S,192], v fp16 [B,H,S,128]
__global__ void build_kf(const __half* __restrict__ kv, const float* __restrict__ ckv,
                         const int* __restrict__ pos_ids,
                         __half* __restrict__ kf, __half* __restrict__ vv) {
    int t = blockIdx.x;
    int b = t / SEQ, s = t % SEQ;
    int tid = threadIdx.x;              // 128
    __shared__ float cs[32], sn[32], kr[64];
    int pos = pos_ids[t];
    if (tid < 32) yarn_cossin(tid, pos, cs[tid], sn[tid]);
    __syncthreads();
    if (tid < 32) {
        float p0 = ckv[(size_t)t * (KVR + DROPE) + KVR + 2 * tid];
        float p1 = ckv[(size_t)t * (KVR + DROPE) + KVR + 2 * tid + 1];
        kr[tid]      = p0 * cs[tid] - p1 * sn[tid];
        kr[tid + 32] = p1 * cs[tid] + p0 * sn[tid];
    }
    __syncthreads();
    for (int h = 0; h < NH; h++) {
        size_t src = (size_t)t * (NH * 256) + h * 256;
        size_t d0 = ((size_t)(b * NH + h) * SEQ + s);
        kf[d0 * DQ + tid] = kv[src + tid];
        vv[d0 * DV + tid] = kv[src + DNOPE + tid];
        if (tid < 64) kf[d0 * DQ + DNOPE + tid] = __float2half_rn(kr[tid]);
    }
}

// ---------------- Tensor-core flash attention (single K/V buffer, 3 CTA/SM)
#define QPITCH 200
#define VPITCH 136
#define ATT_SMEM ((2*64*QPITCH + 64*VPITCH) * 2)
__global__ void __launch_bounds__(128)
attn_tc(const __half* __restrict__ qf, const __half* __restrict__ kf,
        const __half* __restrict__ vv, __half* __restrict__ out) {
    extern __shared__ __half sm[];
    const uint32_t sQ = (uint32_t)__cvta_generic_to_shared(sm);
    const uint32_t sK = sQ + 64 * QPITCH * 2;
    const uint32_t sV = sK + 64 * QPITCH * 2;
    const int tid = threadIdx.x, warp = tid >> 5, lane = tid & 31;
    const int g = lane >> 2, t = lane & 3;
    const int b = blockIdx.z, h = blockIdx.y;
    const int q0 = ((int)gridDim.x - 1 - (int)blockIdx.x) * 64;
    const __half* Qg = qf + (size_t)(b * NH + h) * SEQ * DQ;
    const __half* Kg = kf + (size_t)(b * NH + h) * SEQ * DQ;
    const __half* Vg = vv + (size_t)(b * NH + h) * SEQ * DV;
    const int wrow = warp * 16;
    const float scale = 0.07216878364870323f;    // 192^-0.5

    #pragma unroll
    for (int i = 0; i < 12; i++) {
        int ch = tid + 128 * i;
        int r = ch / 24, c = (ch % 24) * 8;
        uint32_t d = sQ + (uint32_t)(r * QPITCH + c) * 2;
        const __half* src = Qg + (size_t)(q0 + r) * DQ + c;
        asm volatile("cp.async.cg.shared.global [%0], [%1], 16;" :: "r"(d), "l"(src));
    }
    asm volatile("cp.async.commit_group;" ::: "memory");

    float o[16][4];
    #pragma unroll
    for (int i = 0; i < 16; i++)
        #pragma unroll
        for (int c = 0; c < 4; c++) o[i][c] = 0.f;
    float m0 = -INFINITY, m1 = -INFINITY, l0 = 0.f, l1 = 0.f;

    const uint32_t aoff = (uint32_t)((wrow + (lane & 15)) * QPITCH + ((lane >> 4) << 3)) * 2;
    const int brow = ((lane >> 4) << 3) + (lane & 7);
    const int bcol = ((lane >> 3) & 1) << 3;
    const int vrow = lane & 15;
    const int vcol = ((lane >> 4) << 3);

    for (int kc = 0; kc <= q0; kc += 64) {
        __syncthreads();
        #pragma unroll
        for (int i = 0; i < 12; i++) {
            int ch = tid + 128 * i;
            int r = ch / 24, c = (ch % 24) * 8;
            uint32_t d = sK + (uint32_t)(r * QPITCH + c) * 2;
            const __half* src = Kg + (size_t)(kc + r) * DQ + c;
            asm volatile("cp.async.cg.shared.global [%0], [%1], 16;" :: "r"(d), "l"(src));
        }
        #pragma unroll
        for (int i = 0; i < 8; i++) {
            int ch = tid + 128 * i;
            int r = ch / 16, c = (ch % 16) * 8;
            uint32_t d = sV + (uint32_t)(r * VPITCH + c) * 2;
            const __half* src = Vg + (size_t)(kc + r) * DV + c;
            asm volatile("cp.async.cg.shared.global [%0], [%1], 16;" :: "r"(d), "l"(src));
        }
        asm volatile("cp.async.commit_group;" ::: "memory");
        asm volatile("cp.async.wait_group 0;" ::: "memory");
        __syncthreads();

        // ---- S = Q @ K^T ----
        float sacc[8][4];
        #pragma unroll
        for (int nt = 0; nt < 8; nt++)
            #pragma unroll
            for (int c = 0; c < 4; c++) sacc[nt][c] = 0.f;
        #pragma unroll
        for (int kt = 0; kt < 12; kt++) {
            uint32_t a0, a1, a2, a3;
            ldsm4(a0, a1, a2, a3, sQ + aoff + kt * 32);
            uint32_t bf[8][2];
            #pragma unroll
            for (int jj = 0; jj < 4; jj++)
                ldsm4(bf[2 * jj][0], bf[2 * jj][1], bf[2 * jj + 1][0], bf[2 * jj + 1][1],
                      sK + (uint32_t)((jj * 16 + brow) * QPITCH + kt * 16 + bcol) * 2);
            #pragma unroll
            for (int nt = 0; nt < 8; nt++)
                MMA16816(sacc[nt], a0, a1, a2, a3, bf[nt][0], bf[nt][1]);
        }
        int r0w = q0 + wrow + g, r1w = r0w + 8;
        #pragma unroll
        for (int nt = 0; nt < 8; nt++)
            #pragma unroll
            for (int c = 0; c < 4; c++) sacc[nt][c] *= scale;
        if (kc == q0) {
            #pragma unroll
            for (int nt = 0; nt < 8; nt++) {
                int c0 = kc + nt * 8 + 2 * t;
                if (c0     > r0w) sacc[nt][0] = -INFINITY;
                if (c0 + 1 > r0w) sacc[nt][1] = -INFINITY;
                if (c0     > r1w) sacc[nt][2] = -INFINITY;
                if (c0 + 1 > r1w) sacc[nt][3] = -INFINITY;
            }
        }
        // ---- online softmax ----
        float mx0 = -INFINITY, mx1 = -INFINITY;
        #pragma unroll
        for (int nt = 0; nt < 8; nt++) {
            mx0 = fmaxf(mx0, fmaxf(sacc[nt][0], sacc[nt][1]));
            mx1 = fmaxf(mx1, fmaxf(sacc[nt][2], sacc[nt][3]));
        }
        mx0 = fmaxf(mx0, __shfl_xor_sync(0xffffffffu, mx0, 1));
        mx0 = fmaxf(mx0, __shfl_xor_sync(0xffffffffu, mx0, 2));
        mx1 = fmaxf(mx1, __shfl_xor_sync(0xffffffffu, mx1, 1));
        mx1 = fmaxf(mx1, __shfl_xor_sync(0xffffffffu, mx1, 2));
        float nm0 = fmaxf(m0, mx0), nm1 = fmaxf(m1, mx1);
        float cf0 = __expf(m0 - nm0), cf1 = __expf(m1 - nm1);
        float s0 = 0.f, s1 = 0.f;
        uint32_t ph01[8], ph23[8];
        #pragma unroll
        for (int nt = 0; nt < 8; nt++) {
            float p0 = __expf(sacc[nt][0] - nm0);
            float p1 = __expf(sacc[nt][1] - nm0);
            float p2 = __expf(sacc[nt][2] - nm1);
            float p3 = __expf(sacc[nt][3] - nm1);
            s0 += p0 + p1; s1 += p2 + p3;
            __half2 q01 = __floats2half2_rn(p0, p1);
            __half2 q23 = __floats2half2_rn(p2, p3);
            ph01[nt] = *(uint32_t*)&q01;
            ph23[nt] = *(uint32_t*)&q23;
        }
        s0 += __shfl_xor_sync(0xffffffffu, s0, 1);
        s0 += __shfl_xor_sync(0xffffffffu, s0, 2);
        s1 += __shfl_xor_sync(0xffffffffu, s1, 1);
        s1 += __shfl_xor_sync(0xffffffffu, s1, 2);
        l0 = l0 * cf0 + s0;
        l1 = l1 * cf1 + s1;
        m0 = nm0; m1 = nm1;
        #pragma unroll
        for (int nv = 0; nv < 16; nv++) {
            o[nv][0] *= cf0; o[nv][1] *= cf0;
            o[nv][2] *= cf1; o[nv][3] *= cf1;
        }
        // ---- O += P @ V ----
        #pragma unroll
        for (int kt2 = 0; kt2 < 4; kt2++) {
            uint32_t a0 = ph01[2 * kt2], a1 = ph23[2 * kt2];
            uint32_t a2 = ph01[2 * kt2 + 1], a3 = ph23[2 * kt2 + 1];
            #pragma unroll
            for (int jv = 0; jv < 8; jv++) {
                uint32_t b0, b1, b2, b3;
                ldsm4t(b0, b1, b2, b3,
                       sV + (uint32_t)((kt2 * 16 + vrow) * VPITCH + jv * 16 + vcol) * 2);
                MMA16816(o[2 * jv],     a0, a1, a2, a3, b0, b1);
                MMA16816(o[2 * jv + 1], a0, a1, a2, a3, b2, b3);
            }
        }
    }

    float inv0 = 1.f / l0, inv1 = 1.f / l1;
    int r0w = q0 + wrow + g, r1w = r0w + 8;
    #pragma unroll
    for (int nv = 0; nv < 16; nv++) {
        int col = nv * 8 + 2 * t;
        __half2 v0 = __floats2half2_rn(o[nv][0] * inv0, o[nv][1] * inv0);
        __half2 v1 = __floats2half2_rn(o[nv][2] * inv1, o[nv][3] * inv1);
        *(__half2*)&out[(size_t)(b * SEQ + r0w) * (NH * DV) + h * DV + col] = v0;
        *(__half2*)&out[(size_t)(b * SEQ + r1w) * (NH * DV) + h * DV + col] = v1;
    }
}

// ---------------- Launch ----------------
extern "C" void kernel_launch(void* const* d_in, const int* in_sizes, int n_in,
                              void* d_out, int out_size) {
    const float* hidden = (const float*)d_in[0];
    const int*   pos    = (const int*)d_in[1];
    const float* Wq     = (const float*)d_in[2];
    const float* Wkva   = (const float*)d_in[3];
    const float* w_kvln = (const float*)d_in[4];
    const float* Wkvb   = (const float*)d_in[5];
    const float* Wo     = (const float*)d_in[6];
    const float* Wg     = (const float*)d_in[7];
    const float* Wu     = (const float*)d_in[8];
    const float* Wd     = (const float*)d_in[9];
    const float* w_ln1  = (const float*)d_in[10];
    const float* w_ln2  = (const float*)d_in[11];
    float* out = (float*)d_out;

    __half *xln, *cln, *attn, *yh, *ggh, *gh, *qh, *kvh, *qfp, *kfp, *vp;
    __half *wq, *wkva, *wkvb, *wo, *wg, *wu, *wd;
    float *ckv, *x1;
    cudaGetSymbolAddress((void**)&xln,  h_xln);
    cudaGetSymbolAddress((void**)&cln,  h_cln);
    cudaGetSymbolAddress((void**)&attn, h_attn);
    cudaGetSymbolAddress((void**)&yh,   h_y);
    cudaGetSymbolAddress((void**)&ggh,  h_gg);
    cudaGetSymbolAddress((void**)&gh,   h_gh);
    cudaGetSymbolAddress((void**)&qh,   h_q);
    cudaGetSymbolAddress((void**)&kvh,  h_kv);
    cudaGetSymbolAddress((void**)&qfp,  h_qf);
    cudaGetSymbolAddress((void**)&kfp,  h_kf);
    cudaGetSymbolAddress((void**)&vp,   h_v);
    cudaGetSymbolAddress((void**)&wq,   hw_q);
    cudaGetSymbolAddress((void**)&wkva, hw_kva);
    cudaGetSymbolAddress((void**)&wkvb, hw_kvb);
    cudaGetSymbolAddress((void**)&wo,   hw_o);
    cudaGetSymbolAddress((void**)&wg,   hw_g);
    cudaGetSymbolAddress((void**)&wu,   hw_u);
    cudaGetSymbolAddress((void**)&wd,   hw_d);
    cudaGetSymbolAddress((void**)&ckv,  g_ckv);
    cudaGetSymbolAddress((void**)&x1,   g_x1);

    cudaFuncSetAttribute(h16gemm<0>, cudaFuncAttributeMaxDynamicSharedMemorySize, GEMM_SMEM);
    cudaFuncSetAttribute(h16gemm<1>, cudaFuncAttributeMaxDynamicSharedMemorySize, GEMM_SMEM);
    cudaFuncSetAttribute(h16gemm<2>, cudaFuncAttributeMaxDynamicSharedMemorySize, GEMM_SMEM);
    cudaFuncSetAttribute(h16gemm<3>, cudaFuncAttributeMaxDynamicSharedMemorySize, GEMM_SMEM);
    cudaFuncSetAttribute(attn_tc, cudaFuncAttributeMaxDynamicSharedMemorySize, ATT_SMEM);

    dim3 blk(256);
    auto cvt = [&](const float* s, __half* d, int n) {
        int n4 = n / 4;
        int blocks = (n4 + 1023) / 1024;   // 4 x float4 per thread
        w2h_kernel<<<blocks, 256>>>(s, d, n4);
    };
    // launch order: #4 = Wq GEMM (profiled slot)
    cvt(Wq, wq, NH * DQ * HID);                                     // 1
    rmsnorm_kernel<<<NTOK, blk>>>(hidden, w_ln1, xln, HID, HID);    // 2
    cvt(Wkva, wkva, (KVR + DROPE) * HID);                           // 3
    // 4: q = xln @ Wq^T (fp16 out)  [4096 x 3072] K=2048
    h16gemm<2><<<dim3(24, 32), 128, GEMM_SMEM>>>(xln, wq, nullptr, qh, NTOK, NH * DQ, HID);
    // ckv = xln @ Wkva^T (fp32 out)
    h16gemm<0><<<dim3(5, 32), 128, GEMM_SMEM>>>(xln, wkva, nullptr, ckv, NTOK, KVR + DROPE, HID);
    rmsnorm_kernel<<<NTOK, blk>>>(ckv, w_kvln, cln, KVR, KVR + DROPE);
    cvt(Wkvb, wkvb, NH * (DNOPE + DV) * KVR);
    // kv = c_ln @ Wkvb^T (fp16 out)  K=512
    h16gemm<2><<<dim3(32, 32), 128, GEMM_SMEM>>>(cln, wkvb, nullptr, kvh, NTOK, NH * 256, KVR);
    build_qf<<<NTOK, 128>>>(qh, pos, qfp);
    build_kf<<<NTOK, 128>>>(kvh, ckv, pos, kfp, vp);
    // tensor-core flash attention
    attn_tc<<<dim3(SEQ / 64, NH, BATCH), 128, ATT_SMEM>>>(qfp, kfp, vp, attn);
    cvt(Wo, wo, HID * NH * DV);
    // x1 = hidden + attn @ Wo^T
    h16gemm<1><<<dim3(16, 32), 128, GEMM_SMEM>>>(attn, wo, hidden, x1, NTOK, HID, NH * DV);
    rmsnorm_kernel<<<NTOK, blk>>>(x1, w_ln2, yh, HID, HID);
    cvt(Wg, wg, INTER * HID);
    cvt(Wu, wu, INTER * HID);
    cvt(Wd, wd, HID * INTER);
    // g = y @ Wg^T (fp16 out)
    h16gemm<2><<<dim3(86, 32), 128, GEMM_SMEM>>>(yh, wg, nullptr, ggh, NTOK, INTER, HID);
    // gh = silu(g) * (y @ Wu^T)  (fused epilogue, fp16 out)
    h16gemm<3><<<dim3(86, 32), 128, GEMM_SMEM>>>(yh, wu, ggh, gh, NTOK, INTER, HID);
    // out = x1 + gh @ Wd^T  K=10944
    h16gemm<1><<<dim3(16, 32), 128, GEMM_SMEM>>>(gh, wd, x1, out, NTOK, HID, INTER);
}